// round 12
// baseline (speedup 1.0000x reference)
#include <cuda_runtime.h>
#include <cuda_fp16.h>
#include <cstdint>

#define B_  2
#define N_  4096
#define C_  1024
#define H_  16
#define D_  64
#define K_  256
#define HD_ 1024
#define M_  8192

// ---------------- persistent split (big/small) fp16 buffers -------------
__device__ __half h_Xb [M_ * C_],    h_Xs [M_ * C_];
__device__ __half h_Wqb[HD_ * C_],   h_Wqs[HD_ * C_];
__device__ __half h_Wkb[HD_ * C_],   h_Wks[HD_ * C_];
__device__ __half h_Wvb[HD_ * C_],   h_Wvs[HD_ * C_];
__device__ __half h_Web[K_ * N_],    h_Wes[K_ * N_];
__device__ __half h_Wfb[K_ * N_],    h_Wfs[K_ * N_];
__device__ __half h_Wob[C_ * HD_],   h_Wos[C_ * HD_];
__device__ __half h_Qb [M_ * HD_],   h_Qs [M_ * HD_];
__device__ __half h_Ktb[B_ * HD_ * N_], h_Kts[B_ * HD_ * N_];
__device__ __half h_Vtb[B_ * HD_ * N_], h_Vts[B_ * HD_ * N_];
__device__ __half h_KEb[B_ * K_ * HD_], h_KEs[B_ * K_ * HD_];
__device__ __half h_VFb[B_ * HD_ * K_], h_VFs[B_ * HD_ * K_];
__device__ __half h_Ob [M_ * HD_];
__device__ float  g_part[16 * K_ * HD_];   // KE slices 0-7, VF slices 8-15

#define DEV __device__ __forceinline__

DEV uint32_t su32(const void* p) {
    uint32_t a;
    asm("{ .reg .u64 t; cvta.to.shared.u64 t, %1; cvt.u32.u64 %0, t; }" : "=r"(a) : "l"(p));
    return a;
}
DEV void splitf(float x, float y, uint32_t& bo, uint32_t& so) {
    __half hx = __float2half_rn(x), hy = __float2half_rn(y);
    __half2 hb = __halves2half2(hx, hy);
    bo = *(uint32_t*)&hb;
    __half2 hs = __floats2half2_rn(x - __half2float(hx), y - __half2float(hy));
    so = *(uint32_t*)&hs;
}
DEV uint32_t packh2(float x, float y) {
    __half2 h = __floats2half2_rn(x, y);
    return *(uint32_t*)&h;
}

#define CP16(dst, src) asm volatile("cp.async.cg.shared.global [%0], [%1], 16;" :: "r"(dst), "l"(src) : "memory")
#define CPCOMMIT() asm volatile("cp.async.commit_group;" ::: "memory")
#define CPWAIT(n)  asm volatile("cp.async.wait_group %0;" :: "n"(n) : "memory")

#define LDM4(r, a) \
    asm volatile("ldmatrix.sync.aligned.m8n8.x4.shared.b16 {%0,%1,%2,%3}, [%4];" \
        : "=r"((r)[0]), "=r"((r)[1]), "=r"((r)[2]), "=r"((r)[3]) : "r"(a))

DEV void mma16816(float* d, const uint32_t* a, const uint32_t* b) {
    asm volatile("mma.sync.aligned.m16n8k16.row.col.f32.f16.f16.f32 "
        "{%0,%1,%2,%3}, {%4,%5,%6,%7}, {%8,%9}, {%0,%1,%2,%3};"
        : "+f"(d[0]), "+f"(d[1]), "+f"(d[2]), "+f"(d[3])
        : "r"(a[0]), "r"(a[1]), "r"(a[2]), "r"(a[3]), "r"(b[0]), "r"(b[1]));
}

// swizzled byte offset inside a 128x32-half tile (rows of 64B, 16B chunks)
DEV uint32_t tswz(int r, int ch) { return (r << 6) | (((ch ^ ((r >> 1) & 3)) & 3) << 4); }

// ==========================================================================
// one split pass for all fp32 inputs, 4 float4s per thread (MLP=4).
// X: 2M float4 -> 2048 blocks; each weight: 256K float4 -> 256 blocks.
// ==========================================================================
__global__ void split_all(
    const float* X,  __half* Xb,  __half* Xs,
    const float* W0, __half* W0b, __half* W0s,
    const float* W1, __half* W1b, __half* W1s,
    const float* W2, __half* W2b, __half* W2s,
    const float* W3, __half* W3b, __half* W3s,
    const float* W4, __half* W4b, __half* W4s,
    const float* W5, __half* W5b, __half* W5s)
{
    const int bid = blockIdx.x;
    const float* in; __half *ob, *os; int base;
    if (bid < 2048) { in = X; ob = Xb; os = Xs; base = bid; }
    else {
        const int t = bid - 2048, w = t >> 8;
        base = t & 255;
        in = (w == 0) ? W0 : (w == 1) ? W1 : (w == 2) ? W2 : (w == 3) ? W3 : (w == 4) ? W4 : W5;
        ob = (w == 0) ? W0b : (w == 1) ? W1b : (w == 2) ? W2b : (w == 3) ? W3b : (w == 4) ? W4b : W5b;
        os = (w == 0) ? W0s : (w == 1) ? W1s : (w == 2) ? W2s : (w == 3) ? W3s : (w == 4) ? W4s : W5s;
    }
    const int i0 = base * 1024 + threadIdx.x;
    float4 v[4];
#pragma unroll
    for (int j = 0; j < 4; j++) v[j] = ((const float4*)in)[i0 + j * 256];
#pragma unroll
    for (int j = 0; j < 4; j++) {
        uint32_t b0, s0, b1, s1;
        splitf(v[j].x, v[j].y, b0, s0);
        splitf(v[j].z, v[j].w, b1, s1);
        ((uint2*)ob)[i0 + j * 256] = make_uint2(b0, b1);
        ((uint2*)os)[i0 + j * 256] = make_uint2(s0, s1);
    }
}

// ==========================================================================
// shared GEMM body: C[128,128 tile] = Ab * (Bb+Bs)^T, K=1024 (NK=32)
// cp.async 4-stage (CPWAIT(2)), swizzled, 2 CTAs/SM.
// EPI: 0=fp32 (+opt col bias), 1=split-half out
// ==========================================================================
#define GEMM_SMEM 98304   // 4 stages x 24 KB

template<int EPI, int BIASCOL>
DEV void gemm_body(const __half* __restrict__ Agb,
                   const __half* __restrict__ Bgb,
                   const __half* __restrict__ Bgs,
                   const float* __restrict__ bias,
                   float* __restrict__ Cf,
                   __half* __restrict__ Cbh, __half* __restrict__ Csh,
                   int ldA, int ldB, int ldC,
                   int crow0, int ccol0, __half* sh)
{
    const int tid = threadIdx.x, wid = tid >> 5, lane = tid & 31;
    const uint32_t shb = su32(sh);
    const int wm = (wid >> 2) * 64, wn = (wid & 3) * 32;

    float acc[4][4][4];
#pragma unroll
    for (int m = 0; m < 4; m++)
#pragma unroll
        for (int n = 0; n < 4; n++)
#pragma unroll
            for (int j = 0; j < 4; j++) acc[m][n][j] = 0.f;

    // stage layout (bytes): Ab@0, Bb@8192, Bs@16384; stage stride 24576
    auto PREFETCH = [&](int kt, int s) {
        const uint32_t st = shb + s * 24576;
        const int kc = kt * 32;
#pragma unroll
        for (int p = 0; p < 2; p++) {
            const int id = p * 256 + tid;
            const int r = id >> 2, c = id & 3;
            const uint32_t d = st + tswz(r, c);
            const size_t ga = (size_t)r * ldA + kc + c * 8;
            const size_t gb = (size_t)r * ldB + kc + c * 8;
            CP16(d,         Agb + ga);
            CP16(d +  8192, Bgb + gb);
            CP16(d + 16384, Bgs + gb);
        }
    };

    auto COMPUTE = [&](int s) {
        const uint32_t base = shb + s * 24576;
#pragma unroll
        for (int ks2 = 0; ks2 < 2; ks2++) {
            uint32_t ab[4][4];
#pragma unroll
            for (int m = 0; m < 4; m++) {
                const int r = wm + m * 16 + (lane & 15);
                const int ch = ks2 * 2 + (lane >> 4);
                LDM4(ab[m], base + tswz(r, ch));
            }
#pragma unroll
            for (int np = 0; np < 2; np++) {
                const int r = wn + np * 16 + (lane & 7) + 8 * (lane >> 4);
                const int ch = ks2 * 2 + ((lane >> 3) & 1);
                const uint32_t bd = base + 8192 + tswz(r, ch);
                uint32_t bb[4], bs[4];
                LDM4(bb, bd);
                LDM4(bs, bd + 8192);
                // bb terms across accumulators first, then bs terms; per-acc
                // operand order preserved -> bit-identical accumulation.
#pragma unroll
                for (int m = 0; m < 4; m++) mma16816(acc[m][2 * np],     ab[m], bb);
#pragma unroll
                for (int m = 0; m < 4; m++) mma16816(acc[m][2 * np + 1], ab[m], bb + 2);
#pragma unroll
                for (int m = 0; m < 4; m++) mma16816(acc[m][2 * np],     ab[m], bs);
#pragma unroll
                for (int m = 0; m < 4; m++) mma16816(acc[m][2 * np + 1], ab[m], bs + 2);
            }
        }
    };

    const int NK = 32;
    PREFETCH(0, 0); CPCOMMIT();
    PREFETCH(1, 1); CPCOMMIT();
    PREFETCH(2, 2); CPCOMMIT();
    int sc = 0, sp = 3;
    for (int kt = 0; kt < NK; kt++) {
        if (kt + 3 < NK) CPWAIT(2); else CPWAIT(0);
        __syncthreads();
        if (kt + 3 < NK) { PREFETCH(kt + 3, sp); CPCOMMIT(); }
        COMPUTE(sc);
        sc = (sc + 1) & 3;
        sp = (sp + 1) & 3;
    }

    const int row0 = crow0 + wm + (lane >> 2);
    const int col0 = ccol0 + wn + 2 * (lane & 3);
#pragma unroll
    for (int m = 0; m < 4; m++) {
#pragma unroll
        for (int n = 0; n < 4; n++) {
            const int r = row0 + m * 16, c = col0 + n * 8;
            float v0 = acc[m][n][0], v1 = acc[m][n][1];
            float v2 = acc[m][n][2], v3 = acc[m][n][3];
            if (EPI == 0) {
                if (BIASCOL) {
                    const float bc0 = __ldg(&bias[c]), bc1 = __ldg(&bias[c + 1]);
                    v0 += bc0; v1 += bc1; v2 += bc0; v3 += bc1;
                }
                *(float2*)&Cf[(size_t)r * ldC + c]       = make_float2(v0, v1);
                *(float2*)&Cf[(size_t)(r + 8) * ldC + c] = make_float2(v2, v3);
            } else {
                uint32_t b0, s0, b1, s1;
                splitf(v0, v1, b0, s0);
                splitf(v2, v3, b1, s1);
                *(uint32_t*)&Cbh[(size_t)r * ldC + c]       = b0;
                *(uint32_t*)&Csh[(size_t)r * ldC + c]       = s0;
                *(uint32_t*)&Cbh[(size_t)(r + 8) * ldC + c] = b1;
                *(uint32_t*)&Csh[(size_t)(r + 8) * ldC + c] = s1;
            }
        }
    }
}

// ==========================================================================
// merged Q + Kt + Vt: 1536 CTAs in one launch
// ==========================================================================
__global__ void __launch_bounds__(256, 2)
qkv_gemm(const __half* __restrict__ Xb, const __half* __restrict__ Xs,
         const __half* __restrict__ Wqb, const __half* __restrict__ Wqs,
         const __half* __restrict__ Wkb, const __half* __restrict__ Wvb,
         __half* Qb, __half* Qs, __half* Ktb, __half* Kts,
         __half* Vtb, __half* Vts)
{
    extern __shared__ __half sh[];
    const int idx = blockIdx.x;
    if (idx < 512) {
        const int bx = idx & 7, by = idx >> 3;
        gemm_body<1, 0>(Xb + (size_t)by * 128 * 1024,
                        Wqb + (size_t)bx * 128 * 1024,
                        Wqs + (size_t)bx * 128 * 1024,
                        nullptr, nullptr, Qb, Qs,
                        1024, 1024, 1024, by * 128, bx * 128, sh);
    } else {
        const int t = idx - 512;
        const int kv = t >> 9, r = t & 511;
        const int bx = r & 31, by = (r >> 5) & 7, b = r >> 8;
        const __half* A  = (kv ? Wvb : Wkb) + (size_t)by * 128 * 1024;
        const __half* Bb = Xb + (size_t)b * N_ * C_ + (size_t)bx * 128 * 1024;
        const __half* Bs = Xs + (size_t)b * N_ * C_ + (size_t)bx * 128 * 1024;
        __half* Cb = (kv ? Vtb : Ktb) + (size_t)b * HD_ * N_;
        __half* Cs = (kv ? Vts : Kts) + (size_t)b * HD_ * N_;
        gemm_body<1, 0>(A, Bb, Bs, nullptr, nullptr, Cb, Cs,
                        1024, 1024, 4096, by * 128, bx * 128, sh);
    }
}

// ==========================================================================
// merged KE + VF split-K partials: 256 CTAs -> g_part
// ==========================================================================
__global__ void __launch_bounds__(256, 2)
kevf_gemm(const __half* __restrict__ Web,
          const __half* __restrict__ Ktb, const __half* __restrict__ Kts,
          const __half* __restrict__ Vtb,
          const __half* __restrict__ Wfb, const __half* __restrict__ Wfs,
          float* part)
{
    extern __shared__ __half sh[];
    const int idx = blockIdx.x;
    if (idx < 128) {
        const int bx = idx & 7, by = (idx >> 3) & 1, z = idx >> 4;
        const int b = z >> 2, ks = z & 3;
        const __half* A  = Web + ks * 1024 + (size_t)by * 128 * 4096;
        const __half* Bb = Ktb + (size_t)b * HD_ * N_ + ks * 1024 + (size_t)bx * 128 * 4096;
        const __half* Bs = Kts + (size_t)b * HD_ * N_ + ks * 1024 + (size_t)bx * 128 * 4096;
        gemm_body<0, 0>(A, Bb, Bs, nullptr,
                        part + (size_t)z * K_ * HD_, nullptr, nullptr,
                        4096, 4096, 1024, by * 128, bx * 128, sh);
    } else {
        const int t = idx - 128;
        const int bx = t & 1, by = (t >> 1) & 7, z = t >> 4;
        const int b = z >> 2, ks = z & 3;
        const __half* A  = Vtb + (size_t)b * HD_ * N_ + ks * 1024 + (size_t)by * 128 * 4096;
        const __half* Bb = Wfb + ks * 1024 + (size_t)bx * 128 * 4096;
        const __half* Bs = Wfs + ks * 1024 + (size_t)bx * 128 * 4096;
        gemm_body<0, 0>(A, Bb, Bs, nullptr,
                        part + (size_t)(8 + z) * K_ * HD_, nullptr, nullptr,
                        4096, 4096, 256, by * 128, bx * 128, sh);
    }
}

// ==========================================================================
// out projection
// ==========================================================================
__global__ void __launch_bounds__(256, 2)
out_gemm(const __half* __restrict__ Ob_,
         const __half* __restrict__ Wob, const __half* __restrict__ Wos,
         const float* __restrict__ bo, float* __restrict__ out)
{
    extern __shared__ __half sh[];
    const int bx = blockIdx.x, by = blockIdx.y;
    gemm_body<0, 1>(Ob_ + (size_t)by * 128 * 1024,
                    Wob + (size_t)bx * 128 * 1024,
                    Wos + (size_t)bx * 128 * 1024,
                    bo, out, nullptr, nullptr,
                    1024, 1024, 1024, by * 128, bx * 128, sh);
}

// ==========================================================================
// merged split-K reduce + bias -> split halves; 2 chunks/thread (MLP=8)
// ==========================================================================
__global__ void reduce2(const float* __restrict__ part,
                        const float* __restrict__ be, const float* __restrict__ bf,
                        __half* KEb, __half* KEs, __half* VFb, __half* VFs)
{
    const int per = (K_ * HD_) / 4;
    const int b = blockIdx.y;
    const int which = blockIdx.z;

    const float* bias = which ? bf : be;
    __half* ob = which ? VFb : KEb;
    __half* os = which ? VFs : KEs;
    const int cols = which ? K_ : HD_;
    const float4* p = (const float4*)(part + (which ? (size_t)8 * K_ * HD_ : 0))
                      + (size_t)b * 4 * per;

    const int i0 = blockIdx.x * 512 + threadIdx.x;
    float4 v[2][4];
#pragma unroll
    for (int u = 0; u < 2; u++) {
        const int i = i0 + u * 256;
        v[u][0] = p[i];
        v[u][1] = p[per + i];
        v[u][2] = p[2 * per + i];
        v[u][3] = p[3 * per + i];
    }
#pragma unroll
    for (int u = 0; u < 2; u++) {
        const int i = i0 + u * 256;
        float4 a = v[u][0];
        a.x += v[u][1].x + v[u][2].x + v[u][3].x;
        a.y += v[u][1].y + v[u][2].y + v[u][3].y;
        a.z += v[u][1].z + v[u][2].z + v[u][3].z;
        a.w += v[u][1].w + v[u][2].w + v[u][3].w;
        const int e = i * 4;
        if (which) {           // per-column bias
            const int c = e % cols;
            a.x += bias[c]; a.y += bias[c + 1]; a.z += bias[c + 2]; a.w += bias[c + 3];
        } else {               // per-row bias
            const float bb = bias[e / cols];
            a.x += bb; a.y += bb; a.z += bb; a.w += bb;
        }
        uint32_t b0, s0, b1, s1;
        splitf(a.x, a.y, b0, s0);
        splitf(a.z, a.w, b1, s1);
        ((uint2*)ob)[(size_t)b * per + i] = make_uint2(b0, b1);
        ((uint2*)os)[(size_t)b * per + i] = make_uint2(s0, s1);
    }
}

// ==========================================================================
// Fused attention: CTA = (128 rows, head h, batch b), 8 warps
// ==========================================================================
#define QSTR 72
#define VSTR 264
#define OQB 0
#define OKB (128 * QSTR)
#define OKS (OKB + 256 * QSTR)
#define OVB (OKS + 256 * QSTR)
#define OVS (OVB + 64 * VSTR)
#define ATT_SMEM ((OVS + 64 * VSTR) * 2)   // 159744 bytes

__global__ void __launch_bounds__(256, 1)
attn_mma(const __half* __restrict__ Qb, const __half* __restrict__ KEb,
         const __half* __restrict__ KEs, const __half* __restrict__ VFb,
         const __half* __restrict__ VFs, __half* __restrict__ Ob)
{
    extern __shared__ __half sh[];
    const int tid = threadIdx.x, wid = tid >> 5, lane = tid & 31;
    const int b = blockIdx.z, h = blockIdx.y, n0 = blockIdx.x * 128;
    const uint32_t shb = su32(sh);

    const __half* Qgb = Qb  + ((size_t)(b * N_ + n0)) * HD_ + h * D_;
    const __half* Kgb = KEb + ((size_t)b * K_) * HD_ + h * D_;
    const __half* Kgs = KEs + ((size_t)b * K_) * HD_ + h * D_;
    const __half* Vgb = VFb + ((size_t)(b * HD_ + h * D_)) * K_;
    const __half* Vgs = VFs + ((size_t)(b * HD_ + h * D_)) * K_;

#pragma unroll
    for (int p = 0; p < 4; p++) {         // Q: 128 rows x 8 chunks (big only)
        const int id = p * 256 + tid;
        const int r = id >> 3, c = id & 7;
        CP16(shb + OQB * 2 + (r * QSTR + c * 8) * 2, Qgb + (size_t)r * HD_ + c * 8);
    }
#pragma unroll
    for (int p = 0; p < 8; p++) {         // KE: 256 rows x 8 chunks
        const int id = p * 256 + tid;
        const int r = id >> 3, c = id & 7;
        const size_t g = (size_t)r * HD_ + c * 8;
        const uint32_t d = (r * QSTR + c * 8) * 2;
        CP16(shb + OKB * 2 + d, Kgb + g);
        CP16(shb + OKS * 2 + d, Kgs + g);
    }
#pragma unroll
    for (int p = 0; p < 8; p++) {         // VF: 64 rows x 32 chunks
        const int id = p * 256 + tid;
        const int r = id >> 5, c = id & 31;
        const size_t g = (size_t)r * K_ + c * 8;
        const uint32_t d = (r * VSTR + c * 8) * 2;
        CP16(shb + OVB * 2 + d, Vgb + g);
        CP16(shb + OVS * 2 + d, Vgs + g);
    }
    CPCOMMIT();
    CPWAIT(0);
    __syncthreads();

    // ---- scores
    float sacc[32][4];
#pragma unroll
    for (int j = 0; j < 32; j++)
#pragma unroll
        for (int q = 0; q < 4; q++) sacc[j][q] = 0.f;

    const int r0 = wid * 16;
    const uint32_t aoff = ((r0 + (lane & 15)) * QSTR + 8 * (lane >> 4)) * 2;
    const uint32_t boff = (((lane & 7) + 8 * (lane >> 4)) * QSTR + 8 * ((lane >> 3) & 1)) * 2;

#pragma unroll
    for (int ks = 0; ks < 64; ks += 16) {
        uint32_t ab[4];
        LDM4(ab, shb + OQB * 2 + aoff + ks * 2);
#pragma unroll
        for (int np = 0; np < 16; np++) {
            uint32_t kb[4], ksm[4];
            const uint32_t bd = boff + (np * 16 * QSTR + ks) * 2;
            LDM4(kb,  shb + OKB * 2 + bd);
            LDM4(ksm, shb + OKS * 2 + bd);
            mma16816(sacc[2 * np],     ab, kb);
            mma16816(sacc[2 * np + 1], ab, kb + 2);
            mma16816(sacc[2 * np],     ab, ksm);
            mma16816(sacc[2 * np + 1], ab, ksm + 2);
        }
    }

    // ---- softmax
    float mx0 = -1e30f, mx1 = -1e30f;
#pragma unroll
    for (int j = 0; j < 32; j++) {
        mx0 = fmaxf(mx0, fmaxf(sacc[j][0], sacc[j][1]));
        mx1 = fmaxf(mx1, fmaxf(sacc[j][2], sacc[j][3]));
    }
    mx0 = fmaxf(mx0, __shfl_xor_sync(0xffffffffu, mx0, 1));
    mx0 = fmaxf(mx0, __shfl_xor_sync(0xffffffffu, mx0, 2));
    mx1 = fmaxf(mx1, __shfl_xor_sync(0xffffffffu, mx1, 1));
    mx1 = fmaxf(mx1, __shfl_xor_sync(0xffffffffu, mx1, 2));
    float sum0 = 0.f, sum1 = 0.f;
#pragma unroll
    for (int j = 0; j < 32; j++) {
        float e0 = __expf((sacc[j][0] - mx0) * 0.125f);
        float e1 = __expf((sacc[j][1] - mx0) * 0.125f);
        float e2 = __expf((sacc[j][2] - mx1) * 0.125f);
        float e3 = __expf((sacc[j][3] - mx1) * 0.125f);
        sacc[j][0] = e0; sacc[j][1] = e1; sacc[j][2] = e2; sacc[j][3] = e3;
        sum0 += e0 + e1; sum1 += e2 + e3;
    }
    sum0 += __shfl_xor_sync(0xffffffffu, sum0, 1);
    sum0 += __shfl_xor_sync(0xffffffffu, sum0, 2);
    sum1 += __shfl_xor_sync(0xffffffffu, sum1, 1);
    sum1 += __shfl_xor_sync(0xffffffffu, sum1, 2);
    const float inv0 = 1.0f / sum0, inv1 = 1.0f / sum1;
#pragma unroll
    for (int j = 0; j < 32; j++) {
        sacc[j][0] *= inv0; sacc[j][1] *= inv0;
        sacc[j][2] *= inv1; sacc[j][3] *= inv1;
    }

    // ---- PV (P as plain fp16)
    float oacc[8][4];
#pragma unroll
    for (int n = 0; n < 8; n++)
#pragma unroll
        for (int q = 0; q < 4; q++) oacc[n][q] = 0.f;

#pragma unroll
    for (int kt = 0; kt < 16; kt++) {
        uint32_t pa[4];
        pa[0] = packh2(sacc[2 * kt][0],     sacc[2 * kt][1]);
        pa[1] = packh2(sacc[2 * kt][2],     sacc[2 * kt][3]);
        pa[2] = packh2(sacc[2 * kt + 1][0], sacc[2 * kt + 1][1]);
        pa[3] = packh2(sacc[2 * kt + 1][2], sacc[2 * kt + 1][3]);
#pragma unroll
        for (int np = 0; np < 4; np++) {
            const uint32_t bd = (((lane & 7) + 8 * (lane >> 4) + np * 16) * VSTR
                                 + kt * 16 + 8 * ((lane >> 3) & 1)) * 2;
            uint32_t vb[4], vs[4];
            LDM4(vb, shb + OVB * 2 + bd);
            LDM4(vs, shb + OVS * 2 + bd);
            mma16816(oacc[2 * np],     pa, vb);
            mma16816(oacc[2 * np + 1], pa, vb + 2);
            mma16816(oacc[2 * np],     pa, vs);
            mma16816(oacc[2 * np + 1], pa, vs + 2);
        }
    }

    // ---- store O (fp16 big only; out-proj uses A = Ob)
    const int orow = n0 + r0 + (lane >> 2);
    const int ocol = h * D_ + 2 * (lane & 3);
    __half* Obp = Ob + ((size_t)b * N_) * HD_;
#pragma unroll
    for (int n = 0; n < 8; n++) {
        *(uint32_t*)&Obp[(size_t)orow * HD_ + ocol + n * 8]       = packh2(oacc[n][0], oacc[n][1]);
        *(uint32_t*)&Obp[(size_t)(orow + 8) * HD_ + ocol + n * 8] = packh2(oacc[n][2], oacc[n][3]);
    }
}

// ==========================================================================
extern "C" void kernel_launch(void* const* d_in, const int* in_sizes, int n_in,
                              void* d_out, int out_size)
{
    const float* X  = (const float*)d_in[0];
    const float* Wq = (const float*)d_in[1];
    const float* Wk = (const float*)d_in[2];
    const float* Wv = (const float*)d_in[3];
    const float* We = (const float*)d_in[4];
    const float* be = (const float*)d_in[5];
    const float* Wf = (const float*)d_in[6];
    const float* bf = (const float*)d_in[7];
    const float* Wo = (const float*)d_in[8];
    const float* bo = (const float*)d_in[9];
    float* out = (float*)d_out;

    __half *Xb, *Xs, *Wqb, *Wqs, *Wkb, *Wks, *Wvb, *Wvs, *Web, *Wes, *Wfb, *Wfs, *Wob, *Wos;
    __half *Qb, *Qs, *Ktb, *Kts, *Vtb, *Vts, *KEbp, *KEsp, *VFbp, *VFsp, *Obp;
    float* Pp;
    cudaGetSymbolAddress((void**)&Xb,  h_Xb);  cudaGetSymbolAddress((void**)&Xs,  h_Xs);
    cudaGetSymbolAddress((void**)&Wqb, h_Wqb); cudaGetSymbolAddress((void**)&Wqs, h_Wqs);
    cudaGetSymbolAddress((void**)&Wkb, h_Wkb); cudaGetSymbolAddress((void**)&Wks, h_Wks);
    cudaGetSymbolAddress((void**)&Wvb, h_Wvb); cudaGetSymbolAddress((void**)&Wvs, h_Wvs);
    cudaGetSymbolAddress((void**)&Web, h_Web); cudaGetSymbolAddress((void**)&Wes, h_Wes);
    cudaGetSymbolAddress((void**)&Wfb, h_Wfb); cudaGetSymbolAddress((void**)&Wfs, h_Wfs);
    cudaGetSymbolAddress((void**)&Wob, h_Wob); cudaGetSymbolAddress((void**)&Wos, h_Wos);
    cudaGetSymbolAddress((void**)&Qb,  h_Qb);  cudaGetSymbolAddress((void**)&Qs,  h_Qs);
    cudaGetSymbolAddress((void**)&Ktb, h_Ktb); cudaGetSymbolAddress((void**)&Kts, h_Kts);
    cudaGetSymbolAddress((void**)&Vtb, h_Vtb); cudaGetSymbolAddress((void**)&Vts, h_Vts);
    cudaGetSymbolAddress((void**)&KEbp, h_KEb); cudaGetSymbolAddress((void**)&KEsp, h_KEs);
    cudaGetSymbolAddress((void**)&VFbp, h_VFb); cudaGetSymbolAddress((void**)&VFsp, h_VFs);
    cudaGetSymbolAddress((void**)&Obp, h_Ob);
    cudaGetSymbolAddress((void**)&Pp,  g_part);

    cudaFuncSetAttribute(qkv_gemm,  cudaFuncAttributeMaxDynamicSharedMemorySize, GEMM_SMEM);
    cudaFuncSetAttribute(kevf_gemm, cudaFuncAttributeMaxDynamicSharedMemorySize, GEMM_SMEM);
    cudaFuncSetAttribute(out_gemm,  cudaFuncAttributeMaxDynamicSharedMemorySize, GEMM_SMEM);
    cudaFuncSetAttribute(attn_mma,  cudaFuncAttributeMaxDynamicSharedMemorySize, ATT_SMEM);

    // 1) split X + all six weights in one launch (MLP=4 per thread)
    split_all<<<2048 + 6 * 256, 256>>>(
        X, Xb, Xs,
        Wq, Wqb, Wqs, Wk, Wkb, Wks, Wv, Wvb, Wvs,
        We, Web, Wes, Wf, Wfb, Wfs, Wo, Wob, Wos);

    // 2) merged Q + Kt + Vt (1536 CTAs)
    qkv_gemm<<<1536, 256, GEMM_SMEM>>>(Xb, Xs, Wqb, Wqs, Wkb, Wvb,
                                       Qb, Qs, Ktb, Kts, Vtb, Vts);

    // 3) merged KE + VF split-K partials (256 CTAs)
    kevf_gemm<<<256, 256, GEMM_SMEM>>>(Web, Ktb, Kts, Vtb, Wfb, Wfs, Pp);

    // 4) merged reduce (+bias) -> split halves (2 chunks/thread)
    reduce2<<<dim3(128, B_, 2), 256>>>(Pp, be, bf, KEbp, KEsp, VFbp, VFsp);

    // 5) fused attention -> O fp16
    attn_mma<<<dim3(N_ / 128, H_, B_), 256, ATT_SMEM>>>(Qb, KEbp, KEsp, VFbp, VFsp, Obp);

    // 6) out = Ob * (Wo)^T + bo
    out_gemm<<<dim3(8, 64), 256, GEMM_SMEM>>>(Obp, Wob, Wos, bo, out);
}

// round 13
// speedup vs baseline: 1.2498x; 1.2498x over previous
#include <cuda_runtime.h>
#include <cuda_fp16.h>
#include <cstdint>

#define B_  2
#define N_  4096
#define C_  1024
#define H_  16
#define D_  64
#define K_  256
#define HD_ 1024
#define M_  8192

// ---------------- persistent split (big/small) fp16 buffers -------------
__device__ __half h_Xb [M_ * C_],    h_Xs [M_ * C_];
__device__ __half h_Xtb[B_ * C_ * N_], h_Xts[B_ * C_ * N_];   // X^T per batch
__device__ __half h_Wqb[HD_ * C_],   h_Wqs[HD_ * C_];
__device__ __half h_Wkb[HD_ * C_],   h_Wks[HD_ * C_];
__device__ __half h_Wvb[HD_ * C_],   h_Wvs[HD_ * C_];
__device__ __half h_Web[K_ * N_],    h_Wes[K_ * N_];
__device__ __half h_Wfb[K_ * N_],    h_Wfs[K_ * N_];
__device__ __half h_Wob[C_ * HD_],   h_Wos[C_ * HD_];
__device__ __half h_Qb [M_ * HD_];
__device__ __half h_T1b[B_ * K_ * HD_], h_T1s[B_ * K_ * HD_];
__device__ __half h_T2b[B_ * K_ * HD_], h_T2s[B_ * K_ * HD_];
__device__ __half h_KEb[B_ * K_ * HD_], h_KEs[B_ * K_ * HD_];
__device__ __half h_VFb[B_ * HD_ * K_], h_VFs[B_ * HD_ * K_];
__device__ __half h_Ob [M_ * HD_];
__device__ float  g_part[16 * K_ * HD_];   // T1 slices 0-7, T2 slices 8-15

#define DEV __device__ __forceinline__

DEV uint32_t su32(const void* p) {
    uint32_t a;
    asm("{ .reg .u64 t; cvta.to.shared.u64 t, %1; cvt.u32.u64 %0, t; }" : "=r"(a) : "l"(p));
    return a;
}
DEV void splitf(float x, float y, uint32_t& bo, uint32_t& so) {
    __half hx = __float2half_rn(x), hy = __float2half_rn(y);
    __half2 hb = __halves2half2(hx, hy);
    bo = *(uint32_t*)&hb;
    __half2 hs = __floats2half2_rn(x - __half2float(hx), y - __half2float(hy));
    so = *(uint32_t*)&hs;
}
DEV uint32_t packh2(float x, float y) {
    __half2 h = __floats2half2_rn(x, y);
    return *(uint32_t*)&h;
}

#define CP16(dst, src) asm volatile("cp.async.cg.shared.global [%0], [%1], 16;" :: "r"(dst), "l"(src) : "memory")
#define CPCOMMIT() asm volatile("cp.async.commit_group;" ::: "memory")
#define CPWAIT(n)  asm volatile("cp.async.wait_group %0;" :: "n"(n) : "memory")

#define LDM4(r, a) \
    asm volatile("ldmatrix.sync.aligned.m8n8.x4.shared.b16 {%0,%1,%2,%3}, [%4];" \
        : "=r"((r)[0]), "=r"((r)[1]), "=r"((r)[2]), "=r"((r)[3]) : "r"(a))

DEV void mma16816(float* d, const uint32_t* a, const uint32_t* b) {
    asm volatile("mma.sync.aligned.m16n8k16.row.col.f32.f16.f16.f32 "
        "{%0,%1,%2,%3}, {%4,%5,%6,%7}, {%8,%9}, {%0,%1,%2,%3};"
        : "+f"(d[0]), "+f"(d[1]), "+f"(d[2]), "+f"(d[3])
        : "r"(a[0]), "r"(a[1]), "r"(a[2]), "r"(a[3]), "r"(b[0]), "r"(b[1]));
}

// swizzled byte offset inside a 128x32-half tile (rows of 64B, 16B chunks)
DEV uint32_t tswz(int r, int ch) { return (r << 6) | (((ch ^ ((r >> 1) & 3)) & 3) << 4); }

// ==========================================================================
// split pass: X (with transpose, 64x64 tiles, 2048 blocks) + 6 weights
// ==========================================================================
__global__ void split_all(
    const float* X,  __half* Xb,  __half* Xs, __half* Xtb, __half* Xts,
    const float* W0, __half* W0b, __half* W0s,
    const float* W1, __half* W1b, __half* W1s,
    const float* W2, __half* W2b, __half* W2s,
    const float* W3, __half* W3b, __half* W3s,
    const float* W4, __half* W4b, __half* W4s,
    const float* W5, __half* W5b, __half* W5s)
{
    __shared__ float sm[64][68];
    const int bid = blockIdx.x, tid = threadIdx.x;
    if (bid < 2048) {
        const int b = bid >> 10, t = bid & 1023;
        const int n0 = (t >> 4) * 64, c0 = (t & 15) * 64;
        const int r = tid >> 2, q = tid & 3;
        const size_t gf4 = (((size_t)(b * 4096 + n0 + r)) * 1024 + c0) >> 2;
#pragma unroll
        for (int j = 0; j < 4; j++) {
            const int cf4 = q + j * 4;
            float4 v = ((const float4*)X)[gf4 + cf4];
            *(float4*)&sm[r][cf4 * 4] = v;
            uint32_t b0, s0, b1, s1;
            splitf(v.x, v.y, b0, s0);
            splitf(v.z, v.w, b1, s1);
            ((uint2*)Xb)[gf4 + cf4] = make_uint2(b0, b1);
            ((uint2*)Xs)[gf4 + cf4] = make_uint2(s0, s1);
        }
        __syncthreads();
        const size_t tf4 = (((size_t)(b * 1024 + c0 + r)) * 4096 + n0) >> 2;
#pragma unroll
        for (int j = 0; j < 4; j++) {
            const int nf4 = q + j * 4;
            const float f0 = sm[nf4 * 4 + 0][r];
            const float f1 = sm[nf4 * 4 + 1][r];
            const float f2 = sm[nf4 * 4 + 2][r];
            const float f3 = sm[nf4 * 4 + 3][r];
            uint32_t b0, s0, b1, s1;
            splitf(f0, f1, b0, s0);
            splitf(f2, f3, b1, s1);
            ((uint2*)Xtb)[tf4 + nf4] = make_uint2(b0, b1);
            ((uint2*)Xts)[tf4 + nf4] = make_uint2(s0, s1);
        }
    } else {
        const int t = bid - 2048, w = t >> 8, base = t & 255;
        const float* in = (w == 0) ? W0 : (w == 1) ? W1 : (w == 2) ? W2
                        : (w == 3) ? W3 : (w == 4) ? W4 : W5;
        __half* ob = (w == 0) ? W0b : (w == 1) ? W1b : (w == 2) ? W2b
                   : (w == 3) ? W3b : (w == 4) ? W4b : W5b;
        __half* os = (w == 0) ? W0s : (w == 1) ? W1s : (w == 2) ? W2s
                   : (w == 3) ? W3s : (w == 4) ? W4s : W5s;
        const int i0 = base * 1024 + tid;
        float4 v[4];
#pragma unroll
        for (int j = 0; j < 4; j++) v[j] = ((const float4*)in)[i0 + j * 256];
#pragma unroll
        for (int j = 0; j < 4; j++) {
            uint32_t b0, s0, b1, s1;
            splitf(v[j].x, v[j].y, b0, s0);
            splitf(v[j].z, v[j].w, b1, s1);
            ((uint2*)ob)[i0 + j * 256] = make_uint2(b0, b1);
            ((uint2*)os)[i0 + j * 256] = make_uint2(s0, s1);
        }
    }
}

// ==========================================================================
// GEMM body. TERMS=2: C = Ab*(Bb+Bs)^T; TERMS=3: C = (Ab+As)*Bb^T + Ab*Bs^T
// K=1024 (NK=32). TERMS=2: 4 stages x 24 KB; TERMS=3: 3 stages x 32 KB.
// EPI: 0=fp32, 1=split-half pair, 2=big-half only.  BIAS: 0 none/1 col/2 row
// ==========================================================================
#define GEMM_SMEM 98304

template<int EPI, int BIAS, int TERMS>
DEV void gemm_body(const __half* __restrict__ Agb, const __half* __restrict__ Ags,
                   const __half* __restrict__ Bgb, const __half* __restrict__ Bgs,
                   const float* __restrict__ bias,
                   float* __restrict__ Cf,
                   __half* __restrict__ Cbh, __half* __restrict__ Csh,
                   int ldA, int ldB, int ldC,
                   int crow0, int ccol0, __half* sh)
{
    constexpr int SST  = (TERMS == 3) ? 32768 : 24576;
    constexpr int NS   = (TERMS == 3) ? 3 : 4;
    constexpr int OFFB = (TERMS == 3) ? 16384 : 8192;

    const int tid = threadIdx.x, wid = tid >> 5, lane = tid & 31;
    const uint32_t shb = su32(sh);
    const int wm = (wid >> 2) * 64, wn = (wid & 3) * 32;

    float acc[4][4][4];
#pragma unroll
    for (int m = 0; m < 4; m++)
#pragma unroll
        for (int n = 0; n < 4; n++)
#pragma unroll
            for (int j = 0; j < 4; j++) acc[m][n][j] = 0.f;

    auto PREFETCH = [&](int kt, int s) {
        const uint32_t st = shb + s * SST;
        const int kc = kt * 32;
#pragma unroll
        for (int p = 0; p < 2; p++) {
            const int id = p * 256 + tid;
            const int r = id >> 2, c = id & 3;
            const uint32_t d = st + tswz(r, c);
            const size_t ga = (size_t)r * ldA + kc + c * 8;
            const size_t gb = (size_t)r * ldB + kc + c * 8;
            CP16(d, Agb + ga);
            if constexpr (TERMS == 3) CP16(d + 8192, Ags + ga);
            CP16(d + OFFB,        Bgb + gb);
            CP16(d + OFFB + 8192, Bgs + gb);
        }
    };

    auto COMPUTE = [&](int s) {
        const uint32_t base = shb + s * SST;
#pragma unroll
        for (int ks2 = 0; ks2 < 2; ks2++) {
            uint32_t ab[4][4], as_[4][4];
#pragma unroll
            for (int m = 0; m < 4; m++) {
                const int r = wm + m * 16 + (lane & 15);
                const int ch = ks2 * 2 + (lane >> 4);
                LDM4(ab[m], base + tswz(r, ch));
                if constexpr (TERMS == 3) LDM4(as_[m], base + 8192 + tswz(r, ch));
            }
#pragma unroll
            for (int np = 0; np < 2; np++) {
                const int r = wn + np * 16 + (lane & 7) + 8 * (lane >> 4);
                const int ch = ks2 * 2 + ((lane >> 3) & 1);
                const uint32_t bd = base + OFFB + tswz(r, ch);
                uint32_t bb[4], bs[4];
                LDM4(bb, bd);
                LDM4(bs, bd + 8192);
#pragma unroll
                for (int m = 0; m < 4; m++) mma16816(acc[m][2 * np],     ab[m], bb);
#pragma unroll
                for (int m = 0; m < 4; m++) mma16816(acc[m][2 * np + 1], ab[m], bb + 2);
#pragma unroll
                for (int m = 0; m < 4; m++) mma16816(acc[m][2 * np],     ab[m], bs);
#pragma unroll
                for (int m = 0; m < 4; m++) mma16816(acc[m][2 * np + 1], ab[m], bs + 2);
                if constexpr (TERMS == 3) {
#pragma unroll
                    for (int m = 0; m < 4; m++) mma16816(acc[m][2 * np],     as_[m], bb);
#pragma unroll
                    for (int m = 0; m < 4; m++) mma16816(acc[m][2 * np + 1], as_[m], bb + 2);
                }
            }
        }
    };

    const int NK = 32;
#pragma unroll
    for (int s = 0; s < NS - 1; s++) { PREFETCH(s, s); CPCOMMIT(); }
    int sc = 0, sp = NS - 1;
    for (int kt = 0; kt < NK; kt++) {
        if (kt + NS - 1 < NK) CPWAIT(NS - 2); else CPWAIT(0);
        __syncthreads();
        if (kt + NS - 1 < NK) { PREFETCH(kt + NS - 1, sp); CPCOMMIT(); }
        COMPUTE(sc);
        sc = (sc + 1 == NS) ? 0 : sc + 1;
        sp = (sp + 1 == NS) ? 0 : sp + 1;
    }

    const int row0 = crow0 + wm + (lane >> 2);
    const int col0 = ccol0 + wn + 2 * (lane & 3);
#pragma unroll
    for (int m = 0; m < 4; m++) {
#pragma unroll
        for (int n = 0; n < 4; n++) {
            const int r = row0 + m * 16, c = col0 + n * 8;
            float v0 = acc[m][n][0], v1 = acc[m][n][1];
            float v2 = acc[m][n][2], v3 = acc[m][n][3];
            if (BIAS == 1) {
                const float bc0 = __ldg(&bias[c]), bc1 = __ldg(&bias[c + 1]);
                v0 += bc0; v1 += bc1; v2 += bc0; v3 += bc1;
            } else if (BIAS == 2) {
                const float br0 = __ldg(&bias[r]), br8 = __ldg(&bias[r + 8]);
                v0 += br0; v1 += br0; v2 += br8; v3 += br8;
            }
            if (EPI == 0) {
                *(float2*)&Cf[(size_t)r * ldC + c]       = make_float2(v0, v1);
                *(float2*)&Cf[(size_t)(r + 8) * ldC + c] = make_float2(v2, v3);
            } else if (EPI == 1) {
                uint32_t b0, s0, b1, s1;
                splitf(v0, v1, b0, s0);
                splitf(v2, v3, b1, s1);
                *(uint32_t*)&Cbh[(size_t)r * ldC + c]       = b0;
                *(uint32_t*)&Csh[(size_t)r * ldC + c]       = s0;
                *(uint32_t*)&Cbh[(size_t)(r + 8) * ldC + c] = b1;
                *(uint32_t*)&Csh[(size_t)(r + 8) * ldC + c] = s1;
            } else {
                *(uint32_t*)&Cbh[(size_t)r * ldC + c]       = packh2(v0, v1);
                *(uint32_t*)&Cbh[(size_t)(r + 8) * ldC + c] = packh2(v2, v3);
            }
        }
    }
}

// ==========================================================================
// Q = Xb * Wq^T (big-only out): 512 CTAs
// ==========================================================================
__global__ void __launch_bounds__(256, 2)
q_gemm(const __half* __restrict__ Xb,
       const __half* __restrict__ Wqb, const __half* __restrict__ Wqs,
       __half* Qb)
{
    extern __shared__ __half sh[];
    const int bx = blockIdx.x & 7, by = blockIdx.x >> 3;
    gemm_body<2, 0, 2>(Xb + (size_t)by * 128 * 1024, nullptr,
                       Wqb + (size_t)bx * 128 * 1024,
                       Wqs + (size_t)bx * 128 * 1024,
                       nullptr, nullptr, Qb, nullptr,
                       1024, 1024, 1024, by * 128, bx * 128, sh);
}

// ==========================================================================
// T1/T2 split-K partials (3-term): 256 CTAs
//   [0,128):   T1[z] = We[:,ks]*Xt[b][:,ks]^T  [256,1024] -> slices 0-7
//   [128,256): T2[z] = Wf[:,ks]*Xt[b][:,ks]^T  [256,1024] -> slices 8-15
// ==========================================================================
__global__ void __launch_bounds__(256)
t12_gemm(const __half* __restrict__ Web, const __half* __restrict__ Wes,
         const __half* __restrict__ Wfb, const __half* __restrict__ Wfs,
         const __half* __restrict__ Xtb, const __half* __restrict__ Xts,
         float* part)
{
    extern __shared__ __half sh[];
    const int idx = blockIdx.x;
    const int which = idx >> 7, t = idx & 127;
    const int z = t >> 4, r = t & 15;
    const int b = z >> 2, ks = z & 3;
    const int by = r >> 3, bx = r & 7;
    const __half* A  = (which ? Wfb : Web) + ks * 1024 + (size_t)by * 128 * 4096;
    const __half* As = (which ? Wfs : Wes) + ks * 1024 + (size_t)by * 128 * 4096;
    const __half* Bb = Xtb + (size_t)b * C_ * N_ + ks * 1024 + (size_t)bx * 128 * 4096;
    const __half* Bs = Xts + (size_t)b * C_ * N_ + ks * 1024 + (size_t)bx * 128 * 4096;
    gemm_body<0, 0, 3>(A, As, Bb, Bs, nullptr,
                       part + (size_t)(which * 8 + z) * K_ * HD_, nullptr, nullptr,
                       4096, 4096, 1024, by * 128, bx * 128, sh);
}

// ==========================================================================
// reduce T1/T2 partials -> split halves (no bias); 2 chunks/thread
// ==========================================================================
__global__ void reduceT(const float* __restrict__ part,
                        __half* T1b, __half* T1s, __half* T2b, __half* T2s)
{
    const int per = (K_ * HD_) / 4;
    const int b = blockIdx.y, which = blockIdx.z;
    __half* ob = which ? T2b : T1b;
    __half* os = which ? T2s : T1s;
    const float4* p = (const float4*)(part + (size_t)which * 8 * K_ * HD_)
                      + (size_t)b * 4 * per;
    const int i0 = blockIdx.x * 512 + threadIdx.x;
    float4 v[2][4];
#pragma unroll
    for (int u = 0; u < 2; u++) {
        const int i = i0 + u * 256;
        v[u][0] = p[i];
        v[u][1] = p[per + i];
        v[u][2] = p[2 * per + i];
        v[u][3] = p[3 * per + i];
    }
#pragma unroll
    for (int u = 0; u < 2; u++) {
        const int i = i0 + u * 256;
        float4 a = v[u][0];
        a.x += v[u][1].x + v[u][2].x + v[u][3].x;
        a.y += v[u][1].y + v[u][2].y + v[u][3].y;
        a.z += v[u][1].z + v[u][2].z + v[u][3].z;
        a.w += v[u][1].w + v[u][2].w + v[u][3].w;
        uint32_t b0, s0, b1, s1;
        splitf(a.x, a.y, b0, s0);
        splitf(a.z, a.w, b1, s1);
        ((uint2*)ob)[(size_t)b * per + i] = make_uint2(b0, b1);
        ((uint2*)os)[(size_t)b * per + i] = make_uint2(s0, s1);
    }
}

// ==========================================================================
// KE = T1*(Wk)^T + be (row bias) and VFt = Wv*(T2)^T + bf (col bias)
// 64 CTAs, 3-term, split-half outputs
// ==========================================================================
__global__ void __launch_bounds__(256)
kevf2(const __half* __restrict__ T1b, const __half* __restrict__ T1s,
      const __half* __restrict__ T2b, const __half* __restrict__ T2s,
      const __half* __restrict__ Wkb, const __half* __restrict__ Wks,
      const __half* __restrict__ Wvb, const __half* __restrict__ Wvs,
      const float* __restrict__ be, const float* __restrict__ bf,
      __half* KEb, __half* KEs, __half* VFb, __half* VFs)
{
    extern __shared__ __half sh[];
    const int idx = blockIdx.x;
    if (idx < 32) {
        const int b = idx >> 4, r = idx & 15;
        const int by = r >> 3, bx = r & 7;
        gemm_body<1, 2, 3>(T1b + (size_t)b * K_ * HD_ + (size_t)by * 128 * 1024,
                           T1s + (size_t)b * K_ * HD_ + (size_t)by * 128 * 1024,
                           Wkb + (size_t)bx * 128 * 1024,
                           Wks + (size_t)bx * 128 * 1024,
                           be, nullptr,
                           KEb + (size_t)b * K_ * HD_, KEs + (size_t)b * K_ * HD_,
                           1024, 1024, 1024, by * 128, bx * 128, sh);
    } else {
        const int t = idx - 32;
        const int b = t >> 4, r = t & 15;
        const int by = r >> 1, bx = r & 1;
        gemm_body<1, 1, 3>(Wvb + (size_t)by * 128 * 1024,
                           Wvs + (size_t)by * 128 * 1024,
                           T2b + (size_t)b * K_ * HD_ + (size_t)bx * 128 * 1024,
                           T2s + (size_t)b * K_ * HD_ + (size_t)bx * 128 * 1024,
                           bf, nullptr,
                           VFb + (size_t)b * HD_ * K_, VFs + (size_t)b * HD_ * K_,
                           1024, 1024, 256, by * 128, bx * 128, sh);
    }
}

// ==========================================================================
// out projection: 512 CTAs
// ==========================================================================
__global__ void __launch_bounds__(256, 2)
out_gemm(const __half* __restrict__ Ob_,
         const __half* __restrict__ Wob, const __half* __restrict__ Wos,
         const float* __restrict__ bo, float* __restrict__ out)
{
    extern __shared__ __half sh[];
    const int bx = blockIdx.x, by = blockIdx.y;
    gemm_body<0, 1, 2>(Ob_ + (size_t)by * 128 * 1024, nullptr,
                       Wob + (size_t)bx * 128 * 1024,
                       Wos + (size_t)bx * 128 * 1024,
                       bo, out, nullptr, nullptr,
                       1024, 1024, 1024, by * 128, bx * 128, sh);
}

// ==========================================================================
// Fused attention: CTA = (128 rows, head h, batch b), 8 warps
// ==========================================================================
#define QSTR 72
#define VSTR 264
#define OQB 0
#define OKB (128 * QSTR)
#define OKS (OKB + 256 * QSTR)
#define OVB (OKS + 256 * QSTR)
#define OVS (OVB + 64 * VSTR)
#define ATT_SMEM ((OVS + 64 * VSTR) * 2)   // 159744 bytes

__global__ void __launch_bounds__(256, 1)
attn_mma(const __half* __restrict__ Qb, const __half* __restrict__ KEb,
         const __half* __restrict__ KEs, const __half* __restrict__ VFb,
         const __half* __restrict__ VFs, __half* __restrict__ Ob)
{
    extern __shared__ __half sh[];
    const int tid = threadIdx.x, wid = tid >> 5, lane = tid & 31;
    const int b = blockIdx.z, h = blockIdx.y, n0 = blockIdx.x * 128;
    const uint32_t shb = su32(sh);

    const __half* Qgb = Qb  + ((size_t)(b * N_ + n0)) * HD_ + h * D_;
    const __half* Kgb = KEb + ((size_t)b * K_) * HD_ + h * D_;
    const __half* Kgs = KEs + ((size_t)b * K_) * HD_ + h * D_;
    const __half* Vgb = VFb + ((size_t)(b * HD_ + h * D_)) * K_;
    const __half* Vgs = VFs + ((size_t)(b * HD_ + h * D_)) * K_;

#pragma unroll
    for (int p = 0; p < 4; p++) {
        const int id = p * 256 + tid;
        const int r = id >> 3, c = id & 7;
        CP16(shb + OQB * 2 + (r * QSTR + c * 8) * 2, Qgb + (size_t)r * HD_ + c * 8);
    }
#pragma unroll
    for (int p = 0; p < 8; p++) {
        const int id = p * 256 + tid;
        const int r = id >> 3, c = id & 7;
        const size_t g = (size_t)r * HD_ + c * 8;
        const uint32_t d = (r * QSTR + c * 8) * 2;
        CP16(shb + OKB * 2 + d, Kgb + g);
        CP16(shb + OKS * 2 + d, Kgs + g);
    }
#pragma unroll
    for (int p = 0; p < 8; p++) {
        const int id = p * 256 + tid;
        const int r = id >> 5, c = id & 31;
        const size_t g = (size_t)r * K_ + c * 8;
        const uint32_t d = (r * VSTR + c * 8) * 2;
        CP16(shb + OVB * 2 + d, Vgb + g);
        CP16(shb + OVS * 2 + d, Vgs + g);
    }
    CPCOMMIT();
    CPWAIT(0);
    __syncthreads();

    float sacc[32][4];
#pragma unroll
    for (int j = 0; j < 32; j++)
#pragma unroll
        for (int q = 0; q < 4; q++) sacc[j][q] = 0.f;

    const int r0 = wid * 16;
    const uint32_t aoff = ((r0 + (lane & 15)) * QSTR + 8 * (lane >> 4)) * 2;
    const uint32_t boff = (((lane & 7) + 8 * (lane >> 4)) * QSTR + 8 * ((lane >> 3) & 1)) * 2;

#pragma unroll
    for (int ks = 0; ks < 64; ks += 16) {
        uint32_t ab[4];
        LDM4(ab, shb + OQB * 2 + aoff + ks * 2);
#pragma unroll
        for (int np = 0; np < 16; np++) {
            uint32_t kb[4], ksm[4];
            const uint32_t bd = boff + (np * 16 * QSTR + ks) * 2;
            LDM4(kb,  shb + OKB * 2 + bd);
            LDM4(ksm, shb + OKS * 2 + bd);
            mma16816(sacc[2 * np],     ab, kb);
            mma16816(sacc[2 * np + 1], ab, kb + 2);
            mma16816(sacc[2 * np],     ab, ksm);
            mma16816(sacc[2 * np + 1], ab, ksm + 2);
        }
    }

    float mx0 = -1e30f, mx1 = -1e30f;
#pragma unroll
    for (int j = 0; j < 32; j++) {
        mx0 = fmaxf(mx0, fmaxf(sacc[j][0], sacc[j][1]));
        mx1 = fmaxf(mx1, fmaxf(sacc[j][2], sacc[j][3]));
    }
    mx0 = fmaxf(mx0, __shfl_xor_sync(0xffffffffu, mx0, 1));
    mx0 = fmaxf(mx0, __shfl_xor_sync(0xffffffffu, mx0, 2));
    mx1 = fmaxf(mx1, __shfl_xor_sync(0xffffffffu, mx1, 1));
    mx1 = fmaxf(mx1, __shfl_xor_sync(0xffffffffu, mx1, 2));
    float sum0 = 0.f, sum1 = 0.f;
#pragma unroll
    for (int j = 0; j < 32; j++) {
        float e0 = __expf((sacc[j][0] - mx0) * 0.125f);
        float e1 = __expf((sacc[j][1] - mx0) * 0.125f);
        float e2 = __expf((sacc[j][2] - mx1) * 0.125f);
        float e3 = __expf((sacc[j][3] - mx1) * 0.125f);
        sacc[j][0] = e0; sacc[j][1] = e1; sacc[j][2] = e2; sacc[j][3] = e3;
        sum0 += e0 + e1; sum1 += e2 + e3;
    }
    sum0 += __shfl_xor_sync(0xffffffffu, sum0, 1);
    sum0 += __shfl_xor_sync(0xffffffffu, sum0, 2);
    sum1 += __shfl_xor_sync(0xffffffffu, sum1, 1);
    sum1 += __shfl_xor_sync(0xffffffffu, sum1, 2);
    const float inv0 = 1.0f / sum0, inv1 = 1.0f / sum1;
#pragma unroll
    for (int j = 0; j < 32; j++) {
        sacc[j][0] *= inv0; sacc[j][1] *= inv0;
        sacc[j][2] *= inv1; sacc[j][3] *= inv1;
    }

    float oacc[8][4];
#pragma unroll
    for (int n = 0; n < 8; n++)
#pragma unroll
        for (int q = 0; q < 4; q++) oacc[n][q] = 0.f;

#pragma unroll
    for (int kt = 0; kt < 16; kt++) {
        uint32_t pa[4];
        pa[0] = packh2(sacc[2 * kt][0],     sacc[2 * kt][1]);
        pa[1] = packh2(sacc[2 * kt][2],     sacc[2 * kt][3]);
        pa[2] = packh2(sacc[2 * kt + 1][0], sacc[2 * kt + 1][1]);
        pa[3] = packh2(sacc[2 * kt + 1][2], sacc[2 * kt + 1][3]);
#pragma unroll
        for (int np = 0; np < 4; np++) {
            const uint32_t bd = (((lane & 7) + 8 * (lane >> 4) + np * 16) * VSTR
                                 + kt * 16 + 8 * ((lane >> 3) & 1)) * 2;
            uint32_t vb[4], vs[4];
            LDM4(vb, shb + OVB * 2 + bd);
            LDM4(vs, shb + OVS * 2 + bd);
            mma16816(oacc[2 * np],     pa, vb);
            mma16816(oacc[2 * np + 1], pa, vb + 2);
            mma16816(oacc[2 * np],     pa, vs);
            mma16816(oacc[2 * np + 1], pa, vs + 2);
        }
    }

    const int orow = n0 + r0 + (lane >> 2);
    const int ocol = h * D_ + 2 * (lane & 3);
    __half* Obp = Ob + ((size_t)b * N_) * HD_;
#pragma unroll
    for (int n = 0; n < 8; n++) {
        *(uint32_t*)&Obp[(size_t)orow * HD_ + ocol + n * 8]       = packh2(oacc[n][0], oacc[n][1]);
        *(uint32_t*)&Obp[(size_t)(orow + 8) * HD_ + ocol + n * 8] = packh2(oacc[n][2], oacc[n][3]);
    }
}

// ==========================================================================
extern "C" void kernel_launch(void* const* d_in, const int* in_sizes, int n_in,
                              void* d_out, int out_size)
{
    const float* X  = (const float*)d_in[0];
    const float* Wq = (const float*)d_in[1];
    const float* Wk = (const float*)d_in[2];
    const float* Wv = (const float*)d_in[3];
    const float* We = (const float*)d_in[4];
    const float* be = (const float*)d_in[5];
    const float* Wf = (const float*)d_in[6];
    const float* bf = (const float*)d_in[7];
    const float* Wo = (const float*)d_in[8];
    const float* bo = (const float*)d_in[9];
    float* out = (float*)d_out;

    __half *Xb, *Xs, *Xtb, *Xts, *Wqb, *Wqs, *Wkb, *Wks, *Wvb, *Wvs;
    __half *Web, *Wes, *Wfb, *Wfs, *Wob, *Wos, *Qb;
    __half *T1b, *T1s, *T2b, *T2s, *KEbp, *KEsp, *VFbp, *VFsp, *Obp;
    float* Pp;
    cudaGetSymbolAddress((void**)&Xb,  h_Xb);   cudaGetSymbolAddress((void**)&Xs,  h_Xs);
    cudaGetSymbolAddress((void**)&Xtb, h_Xtb);  cudaGetSymbolAddress((void**)&Xts, h_Xts);
    cudaGetSymbolAddress((void**)&Wqb, h_Wqb);  cudaGetSymbolAddress((void**)&Wqs, h_Wqs);
    cudaGetSymbolAddress((void**)&Wkb, h_Wkb);  cudaGetSymbolAddress((void**)&Wks, h_Wks);
    cudaGetSymbolAddress((void**)&Wvb, h_Wvb);  cudaGetSymbolAddress((void**)&Wvs, h_Wvs);
    cudaGetSymbolAddress((void**)&Web, h_Web);  cudaGetSymbolAddress((void**)&Wes, h_Wes);
    cudaGetSymbolAddress((void**)&Wfb, h_Wfb);  cudaGetSymbolAddress((void**)&Wfs, h_Wfs);
    cudaGetSymbolAddress((void**)&Wob, h_Wob);  cudaGetSymbolAddress((void**)&Wos, h_Wos);
    cudaGetSymbolAddress((void**)&Qb,  h_Qb);
    cudaGetSymbolAddress((void**)&T1b, h_T1b);  cudaGetSymbolAddress((void**)&T1s, h_T1s);
    cudaGetSymbolAddress((void**)&T2b, h_T2b);  cudaGetSymbolAddress((void**)&T2s, h_T2s);
    cudaGetSymbolAddress((void**)&KEbp, h_KEb); cudaGetSymbolAddress((void**)&KEsp, h_KEs);
    cudaGetSymbolAddress((void**)&VFbp, h_VFb); cudaGetSymbolAddress((void**)&VFsp, h_VFs);
    cudaGetSymbolAddress((void**)&Obp, h_Ob);
    cudaGetSymbolAddress((void**)&Pp,  g_part);

    cudaFuncSetAttribute(q_gemm,   cudaFuncAttributeMaxDynamicSharedMemorySize, GEMM_SMEM);
    cudaFuncSetAttribute(t12_gemm, cudaFuncAttributeMaxDynamicSharedMemorySize, GEMM_SMEM);
    cudaFuncSetAttribute(kevf2,    cudaFuncAttributeMaxDynamicSharedMemorySize, GEMM_SMEM);
    cudaFuncSetAttribute(out_gemm, cudaFuncAttributeMaxDynamicSharedMemorySize, GEMM_SMEM);
    cudaFuncSetAttribute(attn_mma, cudaFuncAttributeMaxDynamicSharedMemorySize, ATT_SMEM);

    // 1) split X (+transpose) and all weights
    split_all<<<2048 + 6 * 256, 256>>>(
        X, Xb, Xs, Xtb, Xts,
        Wq, Wqb, Wqs, Wk, Wkb, Wks, Wv, Wvb, Wvs,
        We, Web, Wes, Wf, Wfb, Wfs, Wo, Wob, Wos);

    // 2) Q projection (big-only out)
    q_gemm<<<512, 256, GEMM_SMEM>>>(Xb, Wqb, Wqs, Qb);

    // 3) T1 = We*X, T2 = Wf*X (split-K partials, 3-term)
    t12_gemm<<<256, 256, GEMM_SMEM>>>(Web, Wes, Wfb, Wfs, Xtb, Xts, Pp);

    // 4) reduce partials -> T1/T2 split halves
    reduceT<<<dim3(128, B_, 2), 256>>>(Pp, T1b, T1s, T2b, T2s);

    // 5) KE = T1*Wk^T + be, VFt = Wv*T2^T + bf (3-term, split out)
    kevf2<<<64, 256, GEMM_SMEM>>>(T1b, T1s, T2b, T2s, Wkb, Wks, Wvb, Wvs,
                                  be, bf, KEbp, KEsp, VFbp, VFsp);

    // 6) fused attention -> O fp16
    attn_mma<<<dim3(N_ / 128, H_, B_), 256, ATT_SMEM>>>(Qb, KEbp, KEsp, VFbp, VFsp, Obp);

    // 7) out = Ob * Wo^T + bo
    out_gemm<<<dim3(8, 64), 256, GEMM_SMEM>>>(Obp, Wob, Wos, bo, out);
}

// round 14
// speedup vs baseline: 1.4092x; 1.1275x over previous
#include <cuda_runtime.h>
#include <cuda_fp16.h>
#include <cstdint>

#define B_  2
#define N_  4096
#define C_  1024
#define H_  16
#define D_  64
#define K_  256
#define HD_ 1024
#define M_  8192

// ---------------- persistent split (big/small) fp16 buffers -------------
__device__ __half h_Xb [M_ * C_],    h_Xs [M_ * C_];
__device__ __half h_Xtb[B_ * C_ * N_], h_Xts[B_ * C_ * N_];   // X^T per batch
__device__ __half h_Wqb[HD_ * C_],   h_Wqs[HD_ * C_];
__device__ __half h_Wkb[HD_ * C_],   h_Wks[HD_ * C_];
__device__ __half h_Wvb[HD_ * C_],   h_Wvs[HD_ * C_];
__device__ __half h_Web[K_ * N_],    h_Wes[K_ * N_];
__device__ __half h_Wfb[K_ * N_],    h_Wfs[K_ * N_];
__device__ __half h_Wob[C_ * HD_],   h_Wos[C_ * HD_];
__device__ __half h_Qb [M_ * HD_];
__device__ __half h_T1b[B_ * K_ * HD_], h_T1s[B_ * K_ * HD_];
__device__ __half h_T2b[B_ * K_ * HD_], h_T2s[B_ * K_ * HD_];
__device__ __half h_KEb[B_ * K_ * HD_], h_KEs[B_ * K_ * HD_];
__device__ __half h_VFb[B_ * HD_ * K_], h_VFs[B_ * HD_ * K_];
__device__ __half h_Ob [M_ * HD_];
__device__ float  g_part[16 * K_ * HD_];   // T1 slices 0-7, T2 slices 8-15

#define DEV __device__ __forceinline__

DEV uint32_t su32(const void* p) {
    uint32_t a;
    asm("{ .reg .u64 t; cvta.to.shared.u64 t, %1; cvt.u32.u64 %0, t; }" : "=r"(a) : "l"(p));
    return a;
}
DEV void splitf(float x, float y, uint32_t& bo, uint32_t& so) {
    __half hx = __float2half_rn(x), hy = __float2half_rn(y);
    __half2 hb = __halves2half2(hx, hy);
    bo = *(uint32_t*)&hb;
    __half2 hs = __floats2half2_rn(x - __half2float(hx), y - __half2float(hy));
    so = *(uint32_t*)&hs;
}
DEV uint32_t packh2(float x, float y) {
    __half2 h = __floats2half2_rn(x, y);
    return *(uint32_t*)&h;
}

#define CP16(dst, src) asm volatile("cp.async.cg.shared.global [%0], [%1], 16;" :: "r"(dst), "l"(src) : "memory")
#define CPCOMMIT() asm volatile("cp.async.commit_group;" ::: "memory")
#define CPWAIT(n)  asm volatile("cp.async.wait_group %0;" :: "n"(n) : "memory")

#define LDM4(r, a) \
    asm volatile("ldmatrix.sync.aligned.m8n8.x4.shared.b16 {%0,%1,%2,%3}, [%4];" \
        : "=r"((r)[0]), "=r"((r)[1]), "=r"((r)[2]), "=r"((r)[3]) : "r"(a))

DEV void mma16816(float* d, const uint32_t* a, const uint32_t* b) {
    asm volatile("mma.sync.aligned.m16n8k16.row.col.f32.f16.f16.f32 "
        "{%0,%1,%2,%3}, {%4,%5,%6,%7}, {%8,%9}, {%0,%1,%2,%3};"
        : "+f"(d[0]), "+f"(d[1]), "+f"(d[2]), "+f"(d[3])
        : "r"(a[0]), "r"(a[1]), "r"(a[2]), "r"(a[3]), "r"(b[0]), "r"(b[1]));
}

// swizzled byte offset inside a 128x32-half tile (rows of 64B, 16B chunks)
DEV uint32_t tswz(int r, int ch) { return (r << 6) | (((ch ^ ((r >> 1) & 3)) & 3) << 4); }

// ==========================================================================
// split pass: X (with transpose, 64x64 tiles, 2048 blocks) + 6 weights
// ==========================================================================
__global__ void split_all(
    const float* X,  __half* Xb,  __half* Xs, __half* Xtb, __half* Xts,
    const float* W0, __half* W0b, __half* W0s,
    const float* W1, __half* W1b, __half* W1s,
    const float* W2, __half* W2b, __half* W2s,
    const float* W3, __half* W3b, __half* W3s,
    const float* W4, __half* W4b, __half* W4s,
    const float* W5, __half* W5b, __half* W5s)
{
    __shared__ float sm[64][68];
    const int bid = blockIdx.x, tid = threadIdx.x;
    if (bid < 2048) {
        const int b = bid >> 10, t = bid & 1023;
        const int n0 = (t >> 4) * 64, c0 = (t & 15) * 64;
        const int r = tid >> 2, q = tid & 3;
        const size_t gf4 = (((size_t)(b * 4096 + n0 + r)) * 1024 + c0) >> 2;
#pragma unroll
        for (int j = 0; j < 4; j++) {
            const int cf4 = q + j * 4;
            float4 v = ((const float4*)X)[gf4 + cf4];
            *(float4*)&sm[r][cf4 * 4] = v;
            uint32_t b0, s0, b1, s1;
            splitf(v.x, v.y, b0, s0);
            splitf(v.z, v.w, b1, s1);
            ((uint2*)Xb)[gf4 + cf4] = make_uint2(b0, b1);
            ((uint2*)Xs)[gf4 + cf4] = make_uint2(s0, s1);
        }
        __syncthreads();
        const size_t tf4 = (((size_t)(b * 1024 + c0 + r)) * 4096 + n0) >> 2;
#pragma unroll
        for (int j = 0; j < 4; j++) {
            const int nf4 = q + j * 4;
            const float f0 = sm[nf4 * 4 + 0][r];
            const float f1 = sm[nf4 * 4 + 1][r];
            const float f2 = sm[nf4 * 4 + 2][r];
            const float f3 = sm[nf4 * 4 + 3][r];
            uint32_t b0, s0, b1, s1;
            splitf(f0, f1, b0, s0);
            splitf(f2, f3, b1, s1);
            ((uint2*)Xtb)[tf4 + nf4] = make_uint2(b0, b1);
            ((uint2*)Xts)[tf4 + nf4] = make_uint2(s0, s1);
        }
    } else {
        const int t = bid - 2048, w = t >> 8, base = t & 255;
        const float* in = (w == 0) ? W0 : (w == 1) ? W1 : (w == 2) ? W2
                        : (w == 3) ? W3 : (w == 4) ? W4 : W5;
        __half* ob = (w == 0) ? W0b : (w == 1) ? W1b : (w == 2) ? W2b
                   : (w == 3) ? W3b : (w == 4) ? W4b : W5b;
        __half* os = (w == 0) ? W0s : (w == 1) ? W1s : (w == 2) ? W2s
                   : (w == 3) ? W3s : (w == 4) ? W4s : W5s;
        const int i0 = base * 1024 + tid;
        float4 v[4];
#pragma unroll
        for (int j = 0; j < 4; j++) v[j] = ((const float4*)in)[i0 + j * 256];
#pragma unroll
        for (int j = 0; j < 4; j++) {
            uint32_t b0, s0, b1, s1;
            splitf(v[j].x, v[j].y, b0, s0);
            splitf(v[j].z, v[j].w, b1, s1);
            ((uint2*)ob)[i0 + j * 256] = make_uint2(b0, b1);
            ((uint2*)os)[i0 + j * 256] = make_uint2(s0, s1);
        }
    }
}

// ==========================================================================
// GEMM body.
//   TERMS=1: C = Ab*Bb^T                       (4 stages x 16 KB)
//   TERMS=2: C = Ab*(Bb+Bs)^T                  (4 stages x 24 KB)
//   TERMS=3: C = (Ab+As)*Bb^T + Ab*Bs^T        (3 stages x 32 KB)
// K=1024 (NK=32). EPI: 0=fp32, 1=split pair, 2=big only. BIAS: 0/1 col/2 row
// ==========================================================================
#define GEMM_SMEM 98304

template<int EPI, int BIAS, int TERMS>
DEV void gemm_body(const __half* __restrict__ Agb, const __half* __restrict__ Ags,
                   const __half* __restrict__ Bgb, const __half* __restrict__ Bgs,
                   const float* __restrict__ bias,
                   float* __restrict__ Cf,
                   __half* __restrict__ Cbh, __half* __restrict__ Csh,
                   int ldA, int ldB, int ldC,
                   int crow0, int ccol0, __half* sh)
{
    constexpr int SST  = (TERMS == 3) ? 32768 : (TERMS == 2) ? 24576 : 16384;
    constexpr int NS   = (TERMS == 3) ? 3 : 4;
    constexpr int OFFB = (TERMS == 3) ? 16384 : 8192;

    const int tid = threadIdx.x, wid = tid >> 5, lane = tid & 31;
    const uint32_t shb = su32(sh);
    const int wm = (wid >> 2) * 64, wn = (wid & 3) * 32;

    float acc[4][4][4];
#pragma unroll
    for (int m = 0; m < 4; m++)
#pragma unroll
        for (int n = 0; n < 4; n++)
#pragma unroll
            for (int j = 0; j < 4; j++) acc[m][n][j] = 0.f;

    auto PREFETCH = [&](int kt, int s) {
        const uint32_t st = shb + s * SST;
        const int kc = kt * 32;
#pragma unroll
        for (int p = 0; p < 2; p++) {
            const int id = p * 256 + tid;
            const int r = id >> 2, c = id & 3;
            const uint32_t d = st + tswz(r, c);
            const size_t ga = (size_t)r * ldA + kc + c * 8;
            const size_t gb = (size_t)r * ldB + kc + c * 8;
            CP16(d, Agb + ga);
            if constexpr (TERMS == 3) CP16(d + 8192, Ags + ga);
            CP16(d + OFFB, Bgb + gb);
            if constexpr (TERMS >= 2) CP16(d + OFFB + 8192, Bgs + gb);
        }
    };

    auto COMPUTE = [&](int s) {
        const uint32_t base = shb + s * SST;
#pragma unroll
        for (int ks2 = 0; ks2 < 2; ks2++) {
            uint32_t ab[4][4], as_[4][4];
#pragma unroll
            for (int m = 0; m < 4; m++) {
                const int r = wm + m * 16 + (lane & 15);
                const int ch = ks2 * 2 + (lane >> 4);
                LDM4(ab[m], base + tswz(r, ch));
                if constexpr (TERMS == 3) LDM4(as_[m], base + 8192 + tswz(r, ch));
            }
#pragma unroll
            for (int np = 0; np < 2; np++) {
                const int r = wn + np * 16 + (lane & 7) + 8 * (lane >> 4);
                const int ch = ks2 * 2 + ((lane >> 3) & 1);
                const uint32_t bd = base + OFFB + tswz(r, ch);
                uint32_t bb[4], bs[4];
                LDM4(bb, bd);
                if constexpr (TERMS >= 2) LDM4(bs, bd + 8192);
#pragma unroll
                for (int m = 0; m < 4; m++) mma16816(acc[m][2 * np],     ab[m], bb);
#pragma unroll
                for (int m = 0; m < 4; m++) mma16816(acc[m][2 * np + 1], ab[m], bb + 2);
                if constexpr (TERMS >= 2) {
#pragma unroll
                    for (int m = 0; m < 4; m++) mma16816(acc[m][2 * np],     ab[m], bs);
#pragma unroll
                    for (int m = 0; m < 4; m++) mma16816(acc[m][2 * np + 1], ab[m], bs + 2);
                }
                if constexpr (TERMS == 3) {
#pragma unroll
                    for (int m = 0; m < 4; m++) mma16816(acc[m][2 * np],     as_[m], bb);
#pragma unroll
                    for (int m = 0; m < 4; m++) mma16816(acc[m][2 * np + 1], as_[m], bb + 2);
                }
            }
        }
    };

    const int NK = 32;
#pragma unroll
    for (int s = 0; s < NS - 1; s++) { PREFETCH(s, s); CPCOMMIT(); }
    int sc = 0, sp = NS - 1;
    for (int kt = 0; kt < NK; kt++) {
        if (kt + NS - 1 < NK) CPWAIT(NS - 2); else CPWAIT(0);
        __syncthreads();
        if (kt + NS - 1 < NK) { PREFETCH(kt + NS - 1, sp); CPCOMMIT(); }
        COMPUTE(sc);
        sc = (sc + 1 == NS) ? 0 : sc + 1;
        sp = (sp + 1 == NS) ? 0 : sp + 1;
    }

    const int row0 = crow0 + wm + (lane >> 2);
    const int col0 = ccol0 + wn + 2 * (lane & 3);
#pragma unroll
    for (int m = 0; m < 4; m++) {
#pragma unroll
        for (int n = 0; n < 4; n++) {
            const int r = row0 + m * 16, c = col0 + n * 8;
            float v0 = acc[m][n][0], v1 = acc[m][n][1];
            float v2 = acc[m][n][2], v3 = acc[m][n][3];
            if (BIAS == 1) {
                const float bc0 = __ldg(&bias[c]), bc1 = __ldg(&bias[c + 1]);
                v0 += bc0; v1 += bc1; v2 += bc0; v3 += bc1;
            } else if (BIAS == 2) {
                const float br0 = __ldg(&bias[r]), br8 = __ldg(&bias[r + 8]);
                v0 += br0; v1 += br0; v2 += br8; v3 += br8;
            }
            if (EPI == 0) {
                *(float2*)&Cf[(size_t)r * ldC + c]       = make_float2(v0, v1);
                *(float2*)&Cf[(size_t)(r + 8) * ldC + c] = make_float2(v2, v3);
            } else if (EPI == 1) {
                uint32_t b0, s0, b1, s1;
                splitf(v0, v1, b0, s0);
                splitf(v2, v3, b1, s1);
                *(uint32_t*)&Cbh[(size_t)r * ldC + c]       = b0;
                *(uint32_t*)&Csh[(size_t)r * ldC + c]       = s0;
                *(uint32_t*)&Cbh[(size_t)(r + 8) * ldC + c] = b1;
                *(uint32_t*)&Csh[(size_t)(r + 8) * ldC + c] = s1;
            } else {
                *(uint32_t*)&Cbh[(size_t)r * ldC + c]       = packh2(v0, v1);
                *(uint32_t*)&Cbh[(size_t)(r + 8) * ldC + c] = packh2(v2, v3);
            }
        }
    }
}

// ==========================================================================
// merged Q + T1/T2: 768 CTAs
//   [0,512):   Q = Xb * Wq^T (2-term, big-only out)
//   [512,768): T1/T2 split-K partials (3-term, fp32 out)
// ==========================================================================
__global__ void __launch_bounds__(256, 2)
qt12_gemm(const __half* __restrict__ Xb,
          const __half* __restrict__ Wqb, const __half* __restrict__ Wqs,
          const __half* __restrict__ Web, const __half* __restrict__ Wes,
          const __half* __restrict__ Wfb, const __half* __restrict__ Wfs,
          const __half* __restrict__ Xtb, const __half* __restrict__ Xts,
          __half* Qb, float* part)
{
    extern __shared__ __half sh[];
    const int idx = blockIdx.x;
    if (idx < 512) {
        const int bx = idx & 7, by = idx >> 3;
        gemm_body<2, 0, 2>(Xb + (size_t)by * 128 * 1024, nullptr,
                           Wqb + (size_t)bx * 128 * 1024,
                           Wqs + (size_t)bx * 128 * 1024,
                           nullptr, nullptr, Qb, nullptr,
                           1024, 1024, 1024, by * 128, bx * 128, sh);
    } else {
        const int t = idx - 512;
        const int which = t >> 7, u = t & 127;
        const int z = u >> 4, r = u & 15;
        const int b = z >> 2, ks = z & 3;
        const int by = r >> 3, bx = r & 7;
        const __half* A  = (which ? Wfb : Web) + ks * 1024 + (size_t)by * 128 * 4096;
        const __half* As = (which ? Wfs : Wes) + ks * 1024 + (size_t)by * 128 * 4096;
        const __half* Bb = Xtb + (size_t)b * C_ * N_ + ks * 1024 + (size_t)bx * 128 * 4096;
        const __half* Bs = Xts + (size_t)b * C_ * N_ + ks * 1024 + (size_t)bx * 128 * 4096;
        gemm_body<0, 0, 3>(A, As, Bb, Bs, nullptr,
                           part + (size_t)(which * 8 + z) * K_ * HD_, nullptr, nullptr,
                           4096, 4096, 1024, by * 128, bx * 128, sh);
    }
}

// ==========================================================================
// reduce T1/T2 partials -> split halves; 2 chunks/thread
// ==========================================================================
__global__ void reduceT(const float* __restrict__ part,
                        __half* T1b, __half* T1s, __half* T2b, __half* T2s)
{
    const int per = (K_ * HD_) / 4;
    const int b = blockIdx.y, which = blockIdx.z;
    __half* ob = which ? T2b : T1b;
    __half* os = which ? T2s : T1s;
    const float4* p = (const float4*)(part + (size_t)which * 8 * K_ * HD_)
                      + (size_t)b * 4 * per;
    const int i0 = blockIdx.x * 512 + threadIdx.x;
    float4 v[2][4];
#pragma unroll
    for (int u = 0; u < 2; u++) {
        const int i = i0 + u * 256;
        v[u][0] = p[i];
        v[u][1] = p[per + i];
        v[u][2] = p[2 * per + i];
        v[u][3] = p[3 * per + i];
    }
#pragma unroll
    for (int u = 0; u < 2; u++) {
        const int i = i0 + u * 256;
        float4 a = v[u][0];
        a.x += v[u][1].x + v[u][2].x + v[u][3].x;
        a.y += v[u][1].y + v[u][2].y + v[u][3].y;
        a.z += v[u][1].z + v[u][2].z + v[u][3].z;
        a.w += v[u][1].w + v[u][2].w + v[u][3].w;
        uint32_t b0, s0, b1, s1;
        splitf(a.x, a.y, b0, s0);
        splitf(a.z, a.w, b1, s1);
        ((uint2*)ob)[(size_t)b * per + i] = make_uint2(b0, b1);
        ((uint2*)os)[(size_t)b * per + i] = make_uint2(s0, s1);
    }
}

// ==========================================================================
// KE = T1*(Wk)^T + be (row bias), VFt = Wv*(T2)^T + bf (col bias)
// 64 CTAs, 3-term, split-half outputs
// ==========================================================================
__global__ void __launch_bounds__(256)
kevf2(const __half* __restrict__ T1b, const __half* __restrict__ T1s,
      const __half* __restrict__ T2b, const __half* __restrict__ T2s,
      const __half* __restrict__ Wkb, const __half* __restrict__ Wks,
      const __half* __restrict__ Wvb, const __half* __restrict__ Wvs,
      const float* __restrict__ be, const float* __restrict__ bf,
      __half* KEb, __half* KEs, __half* VFb, __half* VFs)
{
    extern __shared__ __half sh[];
    const int idx = blockIdx.x;
    if (idx < 32) {
        const int b = idx >> 4, r = idx & 15;
        const int by = r >> 3, bx = r & 7;
        gemm_body<1, 2, 3>(T1b + (size_t)b * K_ * HD_ + (size_t)by * 128 * 1024,
                           T1s + (size_t)b * K_ * HD_ + (size_t)by * 128 * 1024,
                           Wkb + (size_t)bx * 128 * 1024,
                           Wks + (size_t)bx * 128 * 1024,
                           be, nullptr,
                           KEb + (size_t)b * K_ * HD_, KEs + (size_t)b * K_ * HD_,
                           1024, 1024, 1024, by * 128, bx * 128, sh);
    } else {
        const int t = idx - 32;
        const int b = t >> 4, r = t & 15;
        const int by = r >> 1, bx = r & 1;
        gemm_body<1, 1, 3>(Wvb + (size_t)by * 128 * 1024,
                           Wvs + (size_t)by * 128 * 1024,
                           T2b + (size_t)b * K_ * HD_ + (size_t)bx * 128 * 1024,
                           T2s + (size_t)b * K_ * HD_ + (size_t)bx * 128 * 1024,
                           bf, nullptr,
                           VFb + (size_t)b * HD_ * K_, VFs + (size_t)b * HD_ * K_,
                           1024, 1024, 256, by * 128, bx * 128, sh);
    }
}

// ==========================================================================
// out projection: single-term (Wo big only), 512 CTAs
// ==========================================================================
__global__ void __launch_bounds__(256, 2)
out_gemm(const __half* __restrict__ Ob_,
         const __half* __restrict__ Wob,
         const float* __restrict__ bo, float* __restrict__ out)
{
    extern __shared__ __half sh[];
    const int bx = blockIdx.x, by = blockIdx.y;
    gemm_body<0, 1, 1>(Ob_ + (size_t)by * 128 * 1024, nullptr,
                       Wob + (size_t)bx * 128 * 1024, nullptr,
                       bo, out, nullptr, nullptr,
                       1024, 1024, 1024, by * 128, bx * 128, sh);
}

// ==========================================================================
// Fused attention: CTA = (128 rows, head h, batch b), 8 warps
// ==========================================================================
#define QSTR 72
#define VSTR 264
#define OQB 0
#define OKB (128 * QSTR)
#define OKS (OKB + 256 * QSTR)
#define OVB (OKS + 256 * QSTR)
#define OVS (OVB + 64 * VSTR)
#define ATT_SMEM ((OVS + 64 * VSTR) * 2)   // 159744 bytes

__global__ void __launch_bounds__(256, 1)
attn_mma(const __half* __restrict__ Qb, const __half* __restrict__ KEb,
         const __half* __restrict__ KEs, const __half* __restrict__ VFb,
         const __half* __restrict__ VFs, __half* __restrict__ Ob)
{
    extern __shared__ __half sh[];
    const int tid = threadIdx.x, wid = tid >> 5, lane = tid & 31;
    const int b = blockIdx.z, h = blockIdx.y, n0 = blockIdx.x * 128;
    const uint32_t shb = su32(sh);

    const __half* Qgb = Qb  + ((size_t)(b * N_ + n0)) * HD_ + h * D_;
    const __half* Kgb = KEb + ((size_t)b * K_) * HD_ + h * D_;
    const __half* Kgs = KEs + ((size_t)b * K_) * HD_ + h * D_;
    const __half* Vgb = VFb + ((size_t)(b * HD_ + h * D_)) * K_;
    const __half* Vgs = VFs + ((size_t)(b * HD_ + h * D_)) * K_;

#pragma unroll
    for (int p = 0; p < 4; p++) {
        const int id = p * 256 + tid;
        const int r = id >> 3, c = id & 7;
        CP16(shb + OQB * 2 + (r * QSTR + c * 8) * 2, Qgb + (size_t)r * HD_ + c * 8);
    }
#pragma unroll
    for (int p = 0; p < 8; p++) {
        const int id = p * 256 + tid;
        const int r = id >> 3, c = id & 7;
        const size_t g = (size_t)r * HD_ + c * 8;
        const uint32_t d = (r * QSTR + c * 8) * 2;
        CP16(shb + OKB * 2 + d, Kgb + g);
        CP16(shb + OKS * 2 + d, Kgs + g);
    }
#pragma unroll
    for (int p = 0; p < 8; p++) {
        const int id = p * 256 + tid;
        const int r = id >> 5, c = id & 31;
        const size_t g = (size_t)r * K_ + c * 8;
        const uint32_t d = (r * VSTR + c * 8) * 2;
        CP16(shb + OVB * 2 + d, Vgb + g);
        CP16(shb + OVS * 2 + d, Vgs + g);
    }
    CPCOMMIT();
    CPWAIT(0);
    __syncthreads();

    float sacc[32][4];
#pragma unroll
    for (int j = 0; j < 32; j++)
#pragma unroll
        for (int q = 0; q < 4; q++) sacc[j][q] = 0.f;

    const int r0 = wid * 16;
    const uint32_t aoff = ((r0 + (lane & 15)) * QSTR + 8 * (lane >> 4)) * 2;
    const uint32_t boff = (((lane & 7) + 8 * (lane >> 4)) * QSTR + 8 * ((lane >> 3) & 1)) * 2;

#pragma unroll
    for (int ks = 0; ks < 64; ks += 16) {
        uint32_t ab[4];
        LDM4(ab, shb + OQB * 2 + aoff + ks * 2);
#pragma unroll
        for (int np = 0; np < 16; np++) {
            uint32_t kb[4], ksm[4];
            const uint32_t bd = boff + (np * 16 * QSTR + ks) * 2;
            LDM4(kb,  shb + OKB * 2 + bd);
            LDM4(ksm, shb + OKS * 2 + bd);
            mma16816(sacc[2 * np],     ab, kb);
            mma16816(sacc[2 * np + 1], ab, kb + 2);
            mma16816(sacc[2 * np],     ab, ksm);
            mma16816(sacc[2 * np + 1], ab, ksm + 2);
        }
    }

    float mx0 = -1e30f, mx1 = -1e30f;
#pragma unroll
    for (int j = 0; j < 32; j++) {
        mx0 = fmaxf(mx0, fmaxf(sacc[j][0], sacc[j][1]));
        mx1 = fmaxf(mx1, fmaxf(sacc[j][2], sacc[j][3]));
    }
    mx0 = fmaxf(mx0, __shfl_xor_sync(0xffffffffu, mx0, 1));
    mx0 = fmaxf(mx0, __shfl_xor_sync(0xffffffffu, mx0, 2));
    mx1 = fmaxf(mx1, __shfl_xor_sync(0xffffffffu, mx1, 1));
    mx1 = fmaxf(mx1, __shfl_xor_sync(0xffffffffu, mx1, 2));
    float sum0 = 0.f, sum1 = 0.f;
#pragma unroll
    for (int j = 0; j < 32; j++) {
        float e0 = __expf((sacc[j][0] - mx0) * 0.125f);
        float e1 = __expf((sacc[j][1] - mx0) * 0.125f);
        float e2 = __expf((sacc[j][2] - mx1) * 0.125f);
        float e3 = __expf((sacc[j][3] - mx1) * 0.125f);
        sacc[j][0] = e0; sacc[j][1] = e1; sacc[j][2] = e2; sacc[j][3] = e3;
        sum0 += e0 + e1; sum1 += e2 + e3;
    }
    sum0 += __shfl_xor_sync(0xffffffffu, sum0, 1);
    sum0 += __shfl_xor_sync(0xffffffffu, sum0, 2);
    sum1 += __shfl_xor_sync(0xffffffffu, sum1, 1);
    sum1 += __shfl_xor_sync(0xffffffffu, sum1, 2);
    const float inv0 = 1.0f / sum0, inv1 = 1.0f / sum1;
#pragma unroll
    for (int j = 0; j < 32; j++) {
        sacc[j][0] *= inv0; sacc[j][1] *= inv0;
        sacc[j][2] *= inv1; sacc[j][3] *= inv1;
    }

    float oacc[8][4];
#pragma unroll
    for (int n = 0; n < 8; n++)
#pragma unroll
        for (int q = 0; q < 4; q++) oacc[n][q] = 0.f;

#pragma unroll
    for (int kt = 0; kt < 16; kt++) {
        uint32_t pa[4];
        pa[0] = packh2(sacc[2 * kt][0],     sacc[2 * kt][1]);
        pa[1] = packh2(sacc[2 * kt][2],     sacc[2 * kt][3]);
        pa[2] = packh2(sacc[2 * kt + 1][0], sacc[2 * kt + 1][1]);
        pa[3] = packh2(sacc[2 * kt + 1][2], sacc[2 * kt + 1][3]);
#pragma unroll
        for (int np = 0; np < 4; np++) {
            const uint32_t bd = (((lane & 7) + 8 * (lane >> 4) + np * 16) * VSTR
                                 + kt * 16 + 8 * ((lane >> 3) & 1)) * 2;
            uint32_t vb[4], vs[4];
            LDM4(vb, shb + OVB * 2 + bd);
            LDM4(vs, shb + OVS * 2 + bd);
            mma16816(oacc[2 * np],     pa, vb);
            mma16816(oacc[2 * np + 1], pa, vb + 2);
            mma16816(oacc[2 * np],     pa, vs);
            mma16816(oacc[2 * np + 1], pa, vs + 2);
        }
    }

    const int orow = n0 + r0 + (lane >> 2);
    const int ocol = h * D_ + 2 * (lane & 3);
    __half* Obp = Ob + ((size_t)b * N_) * HD_;
#pragma unroll
    for (int n = 0; n < 8; n++) {
        *(uint32_t*)&Obp[(size_t)orow * HD_ + ocol + n * 8]       = packh2(oacc[n][0], oacc[n][1]);
        *(uint32_t*)&Obp[(size_t)(orow + 8) * HD_ + ocol + n * 8] = packh2(oacc[n][2], oacc[n][3]);
    }
}

// ==========================================================================
extern "C" void kernel_launch(void* const* d_in, const int* in_sizes, int n_in,
                              void* d_out, int out_size)
{
    const float* X  = (const float*)d_in[0];
    const float* Wq = (const float*)d_in[1];
    const float* Wk = (const float*)d_in[2];
    const float* Wv = (const float*)d_in[3];
    const float* We = (const float*)d_in[4];
    const float* be = (const float*)d_in[5];
    const float* Wf = (const float*)d_in[6];
    const float* bf = (const float*)d_in[7];
    const float* Wo = (const float*)d_in[8];
    const float* bo = (const float*)d_in[9];
    float* out = (float*)d_out;

    __half *Xb, *Xs, *Xtb, *Xts, *Wqb, *Wqs, *Wkb, *Wks, *Wvb, *Wvs;
    __half *Web, *Wes, *Wfb, *Wfs, *Wob, *Wos, *Qb;
    __half *T1b, *T1s, *T2b, *T2s, *KEbp, *KEsp, *VFbp, *VFsp, *Obp;
    float* Pp;
    cudaGetSymbolAddress((void**)&Xb,  h_Xb);   cudaGetSymbolAddress((void**)&Xs,  h_Xs);
    cudaGetSymbolAddress((void**)&Xtb, h_Xtb);  cudaGetSymbolAddress((void**)&Xts, h_Xts);
    cudaGetSymbolAddress((void**)&Wqb, h_Wqb);  cudaGetSymbolAddress((void**)&Wqs, h_Wqs);
    cudaGetSymbolAddress((void**)&Wkb, h_Wkb);  cudaGetSymbolAddress((void**)&Wks, h_Wks);
    cudaGetSymbolAddress((void**)&Wvb, h_Wvb);  cudaGetSymbolAddress((void**)&Wvs, h_Wvs);
    cudaGetSymbolAddress((void**)&Web, h_Web);  cudaGetSymbolAddress((void**)&Wes, h_Wes);
    cudaGetSymbolAddress((void**)&Wfb, h_Wfb);  cudaGetSymbolAddress((void**)&Wfs, h_Wfs);
    cudaGetSymbolAddress((void**)&Wob, h_Wob);  cudaGetSymbolAddress((void**)&Wos, h_Wos);
    cudaGetSymbolAddress((void**)&Qb,  h_Qb);
    cudaGetSymbolAddress((void**)&T1b, h_T1b);  cudaGetSymbolAddress((void**)&T1s, h_T1s);
    cudaGetSymbolAddress((void**)&T2b, h_T2b);  cudaGetSymbolAddress((void**)&T2s, h_T2s);
    cudaGetSymbolAddress((void**)&KEbp, h_KEb); cudaGetSymbolAddress((void**)&KEsp, h_KEs);
    cudaGetSymbolAddress((void**)&VFbp, h_VFb); cudaGetSymbolAddress((void**)&VFsp, h_VFs);
    cudaGetSymbolAddress((void**)&Obp, h_Ob);
    cudaGetSymbolAddress((void**)&Pp,  g_part);

    cudaFuncSetAttribute(qt12_gemm, cudaFuncAttributeMaxDynamicSharedMemorySize, GEMM_SMEM);
    cudaFuncSetAttribute(kevf2,     cudaFuncAttributeMaxDynamicSharedMemorySize, GEMM_SMEM);
    cudaFuncSetAttribute(out_gemm,  cudaFuncAttributeMaxDynamicSharedMemorySize, GEMM_SMEM);
    cudaFuncSetAttribute(attn_mma,  cudaFuncAttributeMaxDynamicSharedMemorySize, ATT_SMEM);

    // 1) split X (+transpose) and all weights
    split_all<<<2048 + 6 * 256, 256>>>(
        X, Xb, Xs, Xtb, Xts,
        Wq, Wqb, Wqs, Wk, Wkb, Wks, Wv, Wvb, Wvs,
        We, Web, Wes, Wf, Wfb, Wfs, Wo, Wob, Wos);

    // 2) merged Q + T1/T2 (768 CTAs)
    qt12_gemm<<<768, 256, GEMM_SMEM>>>(Xb, Wqb, Wqs, Web, Wes, Wfb, Wfs,
                                       Xtb, Xts, Qb, Pp);

    // 3) reduce partials -> T1/T2 split halves
    reduceT<<<dim3(128, B_, 2), 256>>>(Pp, T1b, T1s, T2b, T2s);

    // 4) KE = T1*Wk^T + be, VFt = Wv*T2^T + bf (3-term, split out)
    kevf2<<<64, 256, GEMM_SMEM>>>(T1b, T1s, T2b, T2s, Wkb, Wks, Wvb, Wvs,
                                  be, bf, KEbp, KEsp, VFbp, VFsp);

    // 5) fused attention -> O fp16
    attn_mma<<<dim3(N_ / 128, H_, B_), 256, ATT_SMEM>>>(Qb, KEbp, KEsp, VFbp, VFsp, Obp);

    // 6) out = Ob * Wob^T + bo (single-term)
    out_gemm<<<dim3(8, 64), 256, GEMM_SMEM>>>(Obp, Wob, bo, out);
}

// round 15
// speedup vs baseline: 1.4857x; 1.0543x over previous
#include <cuda_runtime.h>
#include <cuda_fp16.h>
#include <cstdint>

#define B_  2
#define N_  4096
#define C_  1024
#define H_  16
#define D_  64
#define K_  256
#define HD_ 1024
#define M_  8192

// ---------------- persistent split (big/small) fp16 buffers -------------
__device__ __half h_Xb [M_ * C_],    h_Xs [M_ * C_];
__device__ __half h_Xtb[B_ * C_ * N_], h_Xts[B_ * C_ * N_];   // X^T per batch
__device__ __half h_Wqb[HD_ * C_],   h_Wqs[HD_ * C_];
__device__ __half h_Wkb[HD_ * C_],   h_Wks[HD_ * C_];
__device__ __half h_Wvb[HD_ * C_],   h_Wvs[HD_ * C_];
__device__ __half h_Web[K_ * N_],    h_Wes[K_ * N_];
__device__ __half h_Wfb[K_ * N_],    h_Wfs[K_ * N_];
__device__ __half h_Wob[C_ * HD_],   h_Wos[C_ * HD_];
__device__ __half h_Qb [M_ * HD_];
__device__ __half h_T1b[B_ * K_ * HD_], h_T1s[B_ * K_ * HD_];
__device__ __half h_T2b[B_ * K_ * HD_], h_T2s[B_ * K_ * HD_];
__device__ __half h_KEb[B_ * K_ * HD_], h_KEs[B_ * K_ * HD_];
__device__ __half h_VFb[B_ * HD_ * K_], h_VFs[B_ * HD_ * K_];
__device__ __half h_Ob [M_ * HD_];
__device__ float  g_part[16 * K_ * HD_];

#define DEV __device__ __forceinline__

DEV uint32_t su32(const void* p) {
    uint32_t a;
    asm("{ .reg .u64 t; cvta.to.shared.u64 t, %1; cvt.u32.u64 %0, t; }" : "=r"(a) : "l"(p));
    return a;
}
DEV void splitf(float x, float y, uint32_t& bo, uint32_t& so) {
    __half hx = __float2half_rn(x), hy = __float2half_rn(y);
    __half2 hb = __halves2half2(hx, hy);
    bo = *(uint32_t*)&hb;
    __half2 hs = __floats2half2_rn(x - __half2float(hx), y - __half2float(hy));
    so = *(uint32_t*)&hs;
}
DEV uint32_t packh2(float x, float y) {
    __half2 h = __floats2half2_rn(x, y);
    return *(uint32_t*)&h;
}

#define CP16(dst, src) asm volatile("cp.async.cg.shared.global [%0], [%1], 16;" :: "r"(dst), "l"(src) : "memory")
#define CPCOMMIT() asm volatile("cp.async.commit_group;" ::: "memory")
#define CPWAIT(n)  asm volatile("cp.async.wait_group %0;" :: "n"(n) : "memory")

#define LDM4(r, a) \
    asm volatile("ldmatrix.sync.aligned.m8n8.x4.shared.b16 {%0,%1,%2,%3}, [%4];" \
        : "=r"((r)[0]), "=r"((r)[1]), "=r"((r)[2]), "=r"((r)[3]) : "r"(a))

DEV void mma16816(float* d, const uint32_t* a, const uint32_t* b) {
    asm volatile("mma.sync.aligned.m16n8k16.row.col.f32.f16.f16.f32 "
        "{%0,%1,%2,%3}, {%4,%5,%6,%7}, {%8,%9}, {%0,%1,%2,%3};"
        : "+f"(d[0]), "+f"(d[1]), "+f"(d[2]), "+f"(d[3])
        : "r"(a[0]), "r"(a[1]), "r"(a[2]), "r"(a[3]), "r"(b[0]), "r"(b[1]));
}

DEV uint32_t tswz(int r, int ch) { return (r << 6) | (((ch ^ ((r >> 1) & 3)) & 3) << 4); }

// ==========================================================================
// split pass: X (with transpose, 64x64 tiles, 2048 blocks) + 6 weights
// ==========================================================================
__global__ void split_all(
    const float* X,  __half* Xb,  __half* Xs, __half* Xtb, __half* Xts,
    const float* W0, __half* W0b, __half* W0s,
    const float* W1, __half* W1b, __half* W1s,
    const float* W2, __half* W2b, __half* W2s,
    const float* W3, __half* W3b, __half* W3s,
    const float* W4, __half* W4b, __half* W4s,
    const float* W5, __half* W5b, __half* W5s)
{
    __shared__ float sm[64][68];
    const int bid = blockIdx.x, tid = threadIdx.x;
    if (bid < 2048) {
        const int b = bid >> 10, t = bid & 1023;
        const int n0 = (t >> 4) * 64, c0 = (t & 15) * 64;
        const int r = tid >> 2, q = tid & 3;
        const size_t gf4 = (((size_t)(b * 4096 + n0 + r)) * 1024 + c0) >> 2;
#pragma unroll
        for (int j = 0; j < 4; j++) {
            const int cf4 = q + j * 4;
            float4 v = ((const float4*)X)[gf4 + cf4];
            *(float4*)&sm[r][cf4 * 4] = v;
            uint32_t b0, s0, b1, s1;
            splitf(v.x, v.y, b0, s0);
            splitf(v.z, v.w, b1, s1);
            ((uint2*)Xb)[gf4 + cf4] = make_uint2(b0, b1);
            ((uint2*)Xs)[gf4 + cf4] = make_uint2(s0, s1);
        }
        __syncthreads();
        const size_t tf4 = (((size_t)(b * 1024 + c0 + r)) * 4096 + n0) >> 2;
#pragma unroll
        for (int j = 0; j < 4; j++) {
            const int nf4 = q + j * 4;
            const float f0 = sm[nf4 * 4 + 0][r];
            const float f1 = sm[nf4 * 4 + 1][r];
            const float f2 = sm[nf4 * 4 + 2][r];
            const float f3 = sm[nf4 * 4 + 3][r];
            uint32_t b0, s0, b1, s1;
            splitf(f0, f1, b0, s0);
            splitf(f2, f3, b1, s1);
            ((uint2*)Xtb)[tf4 + nf4] = make_uint2(b0, b1);
            ((uint2*)Xts)[tf4 + nf4] = make_uint2(s0, s1);
        }
    } else {
        const int t = bid - 2048, w = t >> 8, base = t & 255;
        const float* in = (w == 0) ? W0 : (w == 1) ? W1 : (w == 2) ? W2
                        : (w == 3) ? W3 : (w == 4) ? W4 : W5;
        __half* ob = (w == 0) ? W0b : (w == 1) ? W1b : (w == 2) ? W2b
                   : (w == 3) ? W3b : (w == 4) ? W4b : W5b;
        __half* os = (w == 0) ? W0s : (w == 1) ? W1s : (w == 2) ? W2s
                   : (w == 3) ? W3s : (w == 4) ? W4s : W5s;
        const int i0 = base * 1024 + tid;
        float4 v[4];
#pragma unroll
        for (int j = 0; j < 4; j++) v[j] = ((const float4*)in)[i0 + j * 256];
#pragma unroll
        for (int j = 0; j < 4; j++) {
            uint32_t b0, s0, b1, s1;
            splitf(v[j].x, v[j].y, b0, s0);
            splitf(v[j].z, v[j].w, b1, s1);
            ((uint2*)ob)[i0 + j * 256] = make_uint2(b0, b1);
            ((uint2*)os)[i0 + j * 256] = make_uint2(s0, s1);
        }
    }
}

// ==========================================================================
// GEMM body (runtime NK).
//   TERMS=1: C = Ab*Bb^T; TERMS=2: C = Ab*(Bb+Bs)^T;
//   TERMS=3: C = (Ab+As)*Bb^T + Ab*Bs^T
// EPI: 0=fp32, 1=split pair, 2=big only. BIAS: 0/1 col/2 row
// ==========================================================================
#define GEMM_SMEM 98304

template<int EPI, int BIAS, int TERMS>
DEV void gemm_body(const __half* __restrict__ Agb, const __half* __restrict__ Ags,
                   const __half* __restrict__ Bgb, const __half* __restrict__ Bgs,
                   const float* __restrict__ bias,
                   float* __restrict__ Cf,
                   __half* __restrict__ Cbh, __half* __restrict__ Csh,
                   int ldA, int ldB, int ldC,
                   int crow0, int ccol0, int NK, __half* sh)
{
    constexpr int SST  = (TERMS == 3) ? 32768 : (TERMS == 2) ? 24576 : 16384;
    constexpr int NS   = (TERMS == 3) ? 3 : 4;
    constexpr int OFFB = (TERMS == 3) ? 16384 : 8192;

    const int tid = threadIdx.x, wid = tid >> 5, lane = tid & 31;
    const uint32_t shb = su32(sh);
    const int wm = (wid >> 2) * 64, wn = (wid & 3) * 32;

    float acc[4][4][4];
#pragma unroll
    for (int m = 0; m < 4; m++)
#pragma unroll
        for (int n = 0; n < 4; n++)
#pragma unroll
            for (int j = 0; j < 4; j++) acc[m][n][j] = 0.f;

    auto PREFETCH = [&](int kt, int s) {
        const uint32_t st = shb + s * SST;
        const int kc = kt * 32;
#pragma unroll
        for (int p = 0; p < 2; p++) {
            const int id = p * 256 + tid;
            const int r = id >> 2, c = id & 3;
            const uint32_t d = st + tswz(r, c);
            const size_t ga = (size_t)r * ldA + kc + c * 8;
            const size_t gb = (size_t)r * ldB + kc + c * 8;
            CP16(d, Agb + ga);
            if constexpr (TERMS == 3) CP16(d + 8192, Ags + ga);
            CP16(d + OFFB, Bgb + gb);
            if constexpr (TERMS >= 2) CP16(d + OFFB + 8192, Bgs + gb);
        }
    };

    auto COMPUTE = [&](int s) {
        const uint32_t base = shb + s * SST;
#pragma unroll
        for (int ks2 = 0; ks2 < 2; ks2++) {
            uint32_t ab[4][4], as_[4][4];
#pragma unroll
            for (int m = 0; m < 4; m++) {
                const int r = wm + m * 16 + (lane & 15);
                const int ch = ks2 * 2 + (lane >> 4);
                LDM4(ab[m], base + tswz(r, ch));
                if constexpr (TERMS == 3) LDM4(as_[m], base + 8192 + tswz(r, ch));
            }
#pragma unroll
            for (int np = 0; np < 2; np++) {
                const int r = wn + np * 16 + (lane & 7) + 8 * (lane >> 4);
                const int ch = ks2 * 2 + ((lane >> 3) & 1);
                const uint32_t bd = base + OFFB + tswz(r, ch);
                uint32_t bb[4], bs[4];
                LDM4(bb, bd);
                if constexpr (TERMS >= 2) LDM4(bs, bd + 8192);
#pragma unroll
                for (int m = 0; m < 4; m++) mma16816(acc[m][2 * np],     ab[m], bb);
#pragma unroll
                for (int m = 0; m < 4; m++) mma16816(acc[m][2 * np + 1], ab[m], bb + 2);
                if constexpr (TERMS >= 2) {
#pragma unroll
                    for (int m = 0; m < 4; m++) mma16816(acc[m][2 * np],     ab[m], bs);
#pragma unroll
                    for (int m = 0; m < 4; m++) mma16816(acc[m][2 * np + 1], ab[m], bs + 2);
                }
                if constexpr (TERMS == 3) {
#pragma unroll
                    for (int m = 0; m < 4; m++) mma16816(acc[m][2 * np],     as_[m], bb);
#pragma unroll
                    for (int m = 0; m < 4; m++) mma16816(acc[m][2 * np + 1], as_[m], bb + 2);
                }
            }
        }
    };

#pragma unroll
    for (int s = 0; s < NS - 1; s++) { PREFETCH(s, s); CPCOMMIT(); }
    int sc = 0, sp = NS - 1;
    for (int kt = 0; kt < NK; kt++) {
        if (kt + NS - 1 < NK) CPWAIT(NS - 2); else CPWAIT(0);
        __syncthreads();
        if (kt + NS - 1 < NK) { PREFETCH(kt + NS - 1, sp); CPCOMMIT(); }
        COMPUTE(sc);
        sc = (sc + 1 == NS) ? 0 : sc + 1;
        sp = (sp + 1 == NS) ? 0 : sp + 1;
    }

    const int row0 = crow0 + wm + (lane >> 2);
    const int col0 = ccol0 + wn + 2 * (lane & 3);
#pragma unroll
    for (int m = 0; m < 4; m++) {
#pragma unroll
        for (int n = 0; n < 4; n++) {
            const int r = row0 + m * 16, c = col0 + n * 8;
            float v0 = acc[m][n][0], v1 = acc[m][n][1];
            float v2 = acc[m][n][2], v3 = acc[m][n][3];
            if (BIAS == 1) {
                const float bc0 = __ldg(&bias[c]), bc1 = __ldg(&bias[c + 1]);
                v0 += bc0; v1 += bc1; v2 += bc0; v3 += bc1;
            } else if (BIAS == 2) {
                const float br0 = __ldg(&bias[r]), br8 = __ldg(&bias[r + 8]);
                v0 += br0; v1 += br0; v2 += br8; v3 += br8;
            }
            if (EPI == 0) {
                *(float2*)&Cf[(size_t)r * ldC + c]       = make_float2(v0, v1);
                *(float2*)&Cf[(size_t)(r + 8) * ldC + c] = make_float2(v2, v3);
            } else if (EPI == 1) {
                uint32_t b0, s0, b1, s1;
                splitf(v0, v1, b0, s0);
                splitf(v2, v3, b1, s1);
                *(uint32_t*)&Cbh[(size_t)r * ldC + c]       = b0;
                *(uint32_t*)&Csh[(size_t)r * ldC + c]       = s0;
                *(uint32_t*)&Cbh[(size_t)(r + 8) * ldC + c] = b1;
                *(uint32_t*)&Csh[(size_t)(r + 8) * ldC + c] = s1;
            } else {
                *(uint32_t*)&Cbh[(size_t)r * ldC + c]       = packh2(v0, v1);
                *(uint32_t*)&Cbh[(size_t)(r + 8) * ldC + c] = packh2(v2, v3);
            }
        }
    }
}

// ==========================================================================
// merged Q + T1/T2: 768 CTAs
// ==========================================================================
__global__ void __launch_bounds__(256, 2)
qt12_gemm(const __half* __restrict__ Xb,
          const __half* __restrict__ Wqb, const __half* __restrict__ Wqs,
          const __half* __restrict__ Web, const __half* __restrict__ Wes,
          const __half* __restrict__ Wfb, const __half* __restrict__ Wfs,
          const __half* __restrict__ Xtb, const __half* __restrict__ Xts,
          __half* Qb, float* part)
{
    extern __shared__ __half sh[];
    const int idx = blockIdx.x;
    if (idx < 512) {
        const int bx = idx & 7, by = idx >> 3;
        gemm_body<2, 0, 2>(Xb + (size_t)by * 128 * 1024, nullptr,
                           Wqb + (size_t)bx * 128 * 1024,
                           Wqs + (size_t)bx * 128 * 1024,
                           nullptr, nullptr, Qb, nullptr,
                           1024, 1024, 1024, by * 128, bx * 128, 32, sh);
    } else {
        const int t = idx - 512;
        const int which = t >> 7, u = t & 127;
        const int z = u >> 4, r = u & 15;
        const int b = z >> 2, ks = z & 3;
        const int by = r >> 3, bx = r & 7;
        const __half* A  = (which ? Wfb : Web) + ks * 1024 + (size_t)by * 128 * 4096;
        const __half* As = (which ? Wfs : Wes) + ks * 1024 + (size_t)by * 128 * 4096;
        const __half* Bb = Xtb + (size_t)b * C_ * N_ + ks * 1024 + (size_t)bx * 128 * 4096;
        const __half* Bs = Xts + (size_t)b * C_ * N_ + ks * 1024 + (size_t)bx * 128 * 4096;
        gemm_body<0, 0, 3>(A, As, Bb, Bs, nullptr,
                           part + (size_t)(which * 8 + z) * K_ * HD_, nullptr, nullptr,
                           4096, 4096, 1024, by * 128, bx * 128, 32, sh);
    }
}

// ==========================================================================
// reduce T1/T2 partials -> split halves; 2 chunks/thread
// ==========================================================================
__global__ void reduceT(const float* __restrict__ part,
                        __half* T1b, __half* T1s, __half* T2b, __half* T2s)
{
    const int per = (K_ * HD_) / 4;
    const int b = blockIdx.y, which = blockIdx.z;
    __half* ob = which ? T2b : T1b;
    __half* os = which ? T2s : T1s;
    const float4* p = (const float4*)(part + (size_t)which * 8 * K_ * HD_)
                      + (size_t)b * 4 * per;
    const int i0 = blockIdx.x * 512 + threadIdx.x;
    float4 v[2][4];
#pragma unroll
    for (int u = 0; u < 2; u++) {
        const int i = i0 + u * 256;
        v[u][0] = p[i];
        v[u][1] = p[per + i];
        v[u][2] = p[2 * per + i];
        v[u][3] = p[3 * per + i];
    }
#pragma unroll
    for (int u = 0; u < 2; u++) {
        const int i = i0 + u * 256;
        float4 a = v[u][0];
        a.x += v[u][1].x + v[u][2].x + v[u][3].x;
        a.y += v[u][1].y + v[u][2].y + v[u][3].y;
        a.z += v[u][1].z + v[u][2].z + v[u][3].z;
        a.w += v[u][1].w + v[u][2].w + v[u][3].w;
        uint32_t b0, s0, b1, s1;
        splitf(a.x, a.y, b0, s0);
        splitf(a.z, a.w, b1, s1);
        ((uint2*)ob)[(size_t)b * per + i] = make_uint2(b0, b1);
        ((uint2*)os)[(size_t)b * per + i] = make_uint2(s0, s1);
    }
}

// ==========================================================================
// KE/VF split-K partials (3-term): 256 CTAs, K=1024 -> 4x256 (NK=8)
//   [0,128):   KE[z] partials: T1[b][:,ks]*Wk[:,ks]^T -> slices 0-7, [256,1024]
//   [128,256): VF[z] partials: Wv[:,ks]*T2[b][:,ks]^T -> slices 8-15, [1024,256]
// ==========================================================================
__global__ void __launch_bounds__(256)
kevf2p(const __half* __restrict__ T1b, const __half* __restrict__ T1s,
       const __half* __restrict__ T2b, const __half* __restrict__ T2s,
       const __half* __restrict__ Wkb, const __half* __restrict__ Wks,
       const __half* __restrict__ Wvb, const __half* __restrict__ Wvs,
       float* part)
{
    extern __shared__ __half sh[];
    const int idx = blockIdx.x;
    if (idx < 128) {
        const int bx = idx & 7, by = (idx >> 3) & 1, z = idx >> 4;
        const int b = z >> 2, ks = z & 3;
        const __half* A  = T1b + (size_t)b * K_ * HD_ + (size_t)by * 128 * 1024 + ks * 256;
        const __half* As = T1s + (size_t)b * K_ * HD_ + (size_t)by * 128 * 1024 + ks * 256;
        const __half* Bb = Wkb + (size_t)bx * 128 * 1024 + ks * 256;
        const __half* Bs = Wks + (size_t)bx * 128 * 1024 + ks * 256;
        gemm_body<0, 0, 3>(A, As, Bb, Bs, nullptr,
                           part + (size_t)z * K_ * HD_, nullptr, nullptr,
                           1024, 1024, 1024, by * 128, bx * 128, 8, sh);
    } else {
        const int t = idx - 128;
        const int bx = t & 1, by = (t >> 1) & 7, z = t >> 4;
        const int b = z >> 2, ks = z & 3;
        const __half* A  = Wvb + (size_t)by * 128 * 1024 + ks * 256;
        const __half* As = Wvs + (size_t)by * 128 * 1024 + ks * 256;
        const __half* Bb = T2b + (size_t)b * K_ * HD_ + (size_t)bx * 128 * 1024 + ks * 256;
        const __half* Bs = T2s + (size_t)b * K_ * HD_ + (size_t)bx * 128 * 1024 + ks * 256;
        gemm_body<0, 0, 3>(A, As, Bb, Bs, nullptr,
                           part + (size_t)(8 + z) * K_ * HD_, nullptr, nullptr,
                           1024, 1024, 256, by * 128, bx * 128, 8, sh);
    }
}

// ==========================================================================
// reduce KE/VF partials + bias -> split halves (z=0: KE rowbias, z=1: VF colbias)
// ==========================================================================
__global__ void reduceKV(const float* __restrict__ part,
                         const float* __restrict__ be, const float* __restrict__ bf,
                         __half* KEb, __half* KEs, __half* VFb, __half* VFs)
{
    const int per = (K_ * HD_) / 4;
    const int b = blockIdx.y, which = blockIdx.z;
    const float* bias = which ? bf : be;
    __half* ob = which ? VFb : KEb;
    __half* os = which ? VFs : KEs;
    const float4* p = (const float4*)(part + (size_t)which * 8 * K_ * HD_)
                      + (size_t)b * 4 * per;
    const int i0 = blockIdx.x * 512 + threadIdx.x;
    float4 v[2][4];
#pragma unroll
    for (int u = 0; u < 2; u++) {
        const int i = i0 + u * 256;
        v[u][0] = p[i];
        v[u][1] = p[per + i];
        v[u][2] = p[2 * per + i];
        v[u][3] = p[3 * per + i];
    }
#pragma unroll
    for (int u = 0; u < 2; u++) {
        const int i = i0 + u * 256;
        float4 a = v[u][0];
        a.x += v[u][1].x + v[u][2].x + v[u][3].x;
        a.y += v[u][1].y + v[u][2].y + v[u][3].y;
        a.z += v[u][1].z + v[u][2].z + v[u][3].z;
        a.w += v[u][1].w + v[u][2].w + v[u][3].w;
        const int e = i * 4;
        if (which) {           // VF: [1024,256], per-column bias bf
            const int c = e & (K_ - 1);
            a.x += bias[c]; a.y += bias[c + 1]; a.z += bias[c + 2]; a.w += bias[c + 3];
        } else {               // KE: [256,1024], per-row bias be
            const float bb = bias[e >> 10];
            a.x += bb; a.y += bb; a.z += bb; a.w += bb;
        }
        uint32_t b0, s0, b1, s1;
        splitf(a.x, a.y, b0, s0);
        splitf(a.z, a.w, b1, s1);
        ((uint2*)ob)[(size_t)b * per + i] = make_uint2(b0, b1);
        ((uint2*)os)[(size_t)b * per + i] = make_uint2(s0, s1);
    }
}

// ==========================================================================
// out projection: single-term (Wo big only), 512 CTAs
// ==========================================================================
__global__ void __launch_bounds__(256, 2)
out_gemm(const __half* __restrict__ Ob_,
         const __half* __restrict__ Wob,
         const float* __restrict__ bo, float* __restrict__ out)
{
    extern __shared__ __half sh[];
    const int bx = blockIdx.x, by = blockIdx.y;
    gemm_body<0, 1, 1>(Ob_ + (size_t)by * 128 * 1024, nullptr,
                       Wob + (size_t)bx * 128 * 1024, nullptr,
                       bo, out, nullptr, nullptr,
                       1024, 1024, 1024, by * 128, bx * 128, 32, sh);
}

// ==========================================================================
// Fused attention: CTA = (128 rows, head h, batch b), 8 warps
// ==========================================================================
#define QSTR 72
#define VSTR 264
#define OQB 0
#define OKB (128 * QSTR)
#define OKS (OKB + 256 * QSTR)
#define OVB (OKS + 256 * QSTR)
#define OVS (OVB + 64 * VSTR)
#define ATT_SMEM ((OVS + 64 * VSTR) * 2)   // 159744 bytes

__global__ void __launch_bounds__(256, 1)
attn_mma(const __half* __restrict__ Qb, const __half* __restrict__ KEb,
         const __half* __restrict__ KEs, const __half* __restrict__ VFb,
         const __half* __restrict__ VFs, __half* __restrict__ Ob)
{
    extern __shared__ __half sh[];
    const int tid = threadIdx.x, wid = tid >> 5, lane = tid & 31;
    const int b = blockIdx.z, h = blockIdx.y, n0 = blockIdx.x * 128;
    const uint32_t shb = su32(sh);

    const __half* Qgb = Qb  + ((size_t)(b * N_ + n0)) * HD_ + h * D_;
    const __half* Kgb = KEb + ((size_t)b * K_) * HD_ + h * D_;
    const __half* Kgs = KEs + ((size_t)b * K_) * HD_ + h * D_;
    const __half* Vgb = VFb + ((size_t)(b * HD_ + h * D_)) * K_;
    const __half* Vgs = VFs + ((size_t)(b * HD_ + h * D_)) * K_;

#pragma unroll
    for (int p = 0; p < 4; p++) {
        const int id = p * 256 + tid;
        const int r = id >> 3, c = id & 7;
        CP16(shb + OQB * 2 + (r * QSTR + c * 8) * 2, Qgb + (size_t)r * HD_ + c * 8);
    }
#pragma unroll
    for (int p = 0; p < 8; p++) {
        const int id = p * 256 + tid;
        const int r = id >> 3, c = id & 7;
        const size_t g = (size_t)r * HD_ + c * 8;
        const uint32_t d = (r * QSTR + c * 8) * 2;
        CP16(shb + OKB * 2 + d, Kgb + g);
        CP16(shb + OKS * 2 + d, Kgs + g);
    }
#pragma unroll
    for (int p = 0; p < 8; p++) {
        const int id = p * 256 + tid;
        const int r = id >> 5, c = id & 31;
        const size_t g = (size_t)r * K_ + c * 8;
        const uint32_t d = (r * VSTR + c * 8) * 2;
        CP16(shb + OVB * 2 + d, Vgb + g);
        CP16(shb + OVS * 2 + d, Vgs + g);
    }
    CPCOMMIT();
    CPWAIT(0);
    __syncthreads();

    float sacc[32][4];
#pragma unroll
    for (int j = 0; j < 32; j++)
#pragma unroll
        for (int q = 0; q < 4; q++) sacc[j][q] = 0.f;

    const int r0 = wid * 16;
    const uint32_t aoff = ((r0 + (lane & 15)) * QSTR + 8 * (lane >> 4)) * 2;
    const uint32_t boff = (((lane & 7) + 8 * (lane >> 4)) * QSTR + 8 * ((lane >> 3) & 1)) * 2;

#pragma unroll
    for (int ks = 0; ks < 64; ks += 16) {
        uint32_t ab[4];
        LDM4(ab, shb + OQB * 2 + aoff + ks * 2);
#pragma unroll
        for (int np = 0; np < 16; np++) {
            uint32_t kb[4], ksm[4];
            const uint32_t bd = boff + (np * 16 * QSTR + ks) * 2;
            LDM4(kb,  shb + OKB * 2 + bd);
            LDM4(ksm, shb + OKS * 2 + bd);
            mma16816(sacc[2 * np],     ab, kb);
            mma16816(sacc[2 * np + 1], ab, kb + 2);
            mma16816(sacc[2 * np],     ab, ksm);
            mma16816(sacc[2 * np + 1], ab, ksm + 2);
        }
    }

    float mx0 = -1e30f, mx1 = -1e30f;
#pragma unroll
    for (int j = 0; j < 32; j++) {
        mx0 = fmaxf(mx0, fmaxf(sacc[j][0], sacc[j][1]));
        mx1 = fmaxf(mx1, fmaxf(sacc[j][2], sacc[j][3]));
    }
    mx0 = fmaxf(mx0, __shfl_xor_sync(0xffffffffu, mx0, 1));
    mx0 = fmaxf(mx0, __shfl_xor_sync(0xffffffffu, mx0, 2));
    mx1 = fmaxf(mx1, __shfl_xor_sync(0xffffffffu, mx1, 1));
    mx1 = fmaxf(mx1, __shfl_xor_sync(0xffffffffu, mx1, 2));
    float sum0 = 0.f, sum1 = 0.f;
#pragma unroll
    for (int j = 0; j < 32; j++) {
        float e0 = __expf((sacc[j][0] - mx0) * 0.125f);
        float e1 = __expf((sacc[j][1] - mx0) * 0.125f);
        float e2 = __expf((sacc[j][2] - mx1) * 0.125f);
        float e3 = __expf((sacc[j][3] - mx1) * 0.125f);
        sacc[j][0] = e0; sacc[j][1] = e1; sacc[j][2] = e2; sacc[j][3] = e3;
        sum0 += e0 + e1; sum1 += e2 + e3;
    }
    sum0 += __shfl_xor_sync(0xffffffffu, sum0, 1);
    sum0 += __shfl_xor_sync(0xffffffffu, sum0, 2);
    sum1 += __shfl_xor_sync(0xffffffffu, sum1, 1);
    sum1 += __shfl_xor_sync(0xffffffffu, sum1, 2);
    const float inv0 = 1.0f / sum0, inv1 = 1.0f / sum1;
#pragma unroll
    for (int j = 0; j < 32; j++) {
        sacc[j][0] *= inv0; sacc[j][1] *= inv0;
        sacc[j][2] *= inv1; sacc[j][3] *= inv1;
    }

    float oacc[8][4];
#pragma unroll
    for (int n = 0; n < 8; n++)
#pragma unroll
        for (int q = 0; q < 4; q++) oacc[n][q] = 0.f;

#pragma unroll
    for (int kt = 0; kt < 16; kt++) {
        uint32_t pa[4];
        pa[0] = packh2(sacc[2 * kt][0],     sacc[2 * kt][1]);
        pa[1] = packh2(sacc[2 * kt][2],     sacc[2 * kt][3]);
        pa[2] = packh2(sacc[2 * kt + 1][0], sacc[2 * kt + 1][1]);
        pa[3] = packh2(sacc[2 * kt + 1][2], sacc[2 * kt + 1][3]);
#pragma unroll
        for (int np = 0; np < 4; np++) {
            const uint32_t bd = (((lane & 7) + 8 * (lane >> 4) + np * 16) * VSTR
                                 + kt * 16 + 8 * ((lane >> 3) & 1)) * 2;
            uint32_t vb[4], vs[4];
            LDM4(vb, shb + OVB * 2 + bd);
            LDM4(vs, shb + OVS * 2 + bd);
            mma16816(oacc[2 * np],     pa, vb);
            mma16816(oacc[2 * np + 1], pa, vb + 2);
            mma16816(oacc[2 * np],     pa, vs);
            mma16816(oacc[2 * np + 1], pa, vs + 2);
        }
    }

    const int orow = n0 + r0 + (lane >> 2);
    const int ocol = h * D_ + 2 * (lane & 3);
    __half* Obp = Ob + ((size_t)b * N_) * HD_;
#pragma unroll
    for (int n = 0; n < 8; n++) {
        *(uint32_t*)&Obp[(size_t)orow * HD_ + ocol + n * 8]       = packh2(oacc[n][0], oacc[n][1]);
        *(uint32_t*)&Obp[(size_t)(orow + 8) * HD_ + ocol + n * 8] = packh2(oacc[n][2], oacc[n][3]);
    }
}

// ==========================================================================
extern "C" void kernel_launch(void* const* d_in, const int* in_sizes, int n_in,
                              void* d_out, int out_size)
{
    const float* X  = (const float*)d_in[0];
    const float* Wq = (const float*)d_in[1];
    const float* Wk = (const float*)d_in[2];
    const float* Wv = (const float*)d_in[3];
    const float* We = (const float*)d_in[4];
    const float* be = (const float*)d_in[5];
    const float* Wf = (const float*)d_in[6];
    const float* bf = (const float*)d_in[7];
    const float* Wo = (const float*)d_in[8];
    const float* bo = (const float*)d_in[9];
    float* out = (float*)d_out;

    __half *Xb, *Xs, *Xtb, *Xts, *Wqb, *Wqs, *Wkb, *Wks, *Wvb, *Wvs;
    __half *Web, *Wes, *Wfb, *Wfs, *Wob, *Wos, *Qb;
    __half *T1b, *T1s, *T2b, *T2s, *KEbp, *KEsp, *VFbp, *VFsp, *Obp;
    float* Pp;
    cudaGetSymbolAddress((void**)&Xb,  h_Xb);   cudaGetSymbolAddress((void**)&Xs,  h_Xs);
    cudaGetSymbolAddress((void**)&Xtb, h_Xtb);  cudaGetSymbolAddress((void**)&Xts, h_Xts);
    cudaGetSymbolAddress((void**)&Wqb, h_Wqb);  cudaGetSymbolAddress((void**)&Wqs, h_Wqs);
    cudaGetSymbolAddress((void**)&Wkb, h_Wkb);  cudaGetSymbolAddress((void**)&Wks, h_Wks);
    cudaGetSymbolAddress((void**)&Wvb, h_Wvb);  cudaGetSymbolAddress((void**)&Wvs, h_Wvs);
    cudaGetSymbolAddress((void**)&Web, h_Web);  cudaGetSymbolAddress((void**)&Wes, h_Wes);
    cudaGetSymbolAddress((void**)&Wfb, h_Wfb);  cudaGetSymbolAddress((void**)&Wfs, h_Wfs);
    cudaGetSymbolAddress((void**)&Wob, h_Wob);  cudaGetSymbolAddress((void**)&Wos, h_Wos);
    cudaGetSymbolAddress((void**)&Qb,  h_Qb);
    cudaGetSymbolAddress((void**)&T1b, h_T1b);  cudaGetSymbolAddress((void**)&T1s, h_T1s);
    cudaGetSymbolAddress((void**)&T2b, h_T2b);  cudaGetSymbolAddress((void**)&T2s, h_T2s);
    cudaGetSymbolAddress((void**)&KEbp, h_KEb); cudaGetSymbolAddress((void**)&KEsp, h_KEs);
    cudaGetSymbolAddress((void**)&VFbp, h_VFb); cudaGetSymbolAddress((void**)&VFsp, h_VFs);
    cudaGetSymbolAddress((void**)&Obp, h_Ob);
    cudaGetSymbolAddress((void**)&Pp,  g_part);

    cudaFuncSetAttribute(qt12_gemm, cudaFuncAttributeMaxDynamicSharedMemorySize, GEMM_SMEM);
    cudaFuncSetAttribute(kevf2p,    cudaFuncAttributeMaxDynamicSharedMemorySize, GEMM_SMEM);
    cudaFuncSetAttribute(out_gemm,  cudaFuncAttributeMaxDynamicSharedMemorySize, GEMM_SMEM);
    cudaFuncSetAttribute(attn_mma,  cudaFuncAttributeMaxDynamicSharedMemorySize, ATT_SMEM);

    // 1) split X (+transpose) and all weights
    split_all<<<2048 + 6 * 256, 256>>>(
        X, Xb, Xs, Xtb, Xts,
        Wq, Wqb, Wqs, Wk, Wkb, Wks, Wv, Wvb, Wvs,
        We, Web, Wes, Wf, Wfb, Wfs, Wo, Wob, Wos);

    // 2) merged Q + T1/T2 (768 CTAs)
    qt12_gemm<<<768, 256, GEMM_SMEM>>>(Xb, Wqb, Wqs, Web, Wes, Wfb, Wfs,
                                       Xtb, Xts, Qb, Pp);

    // 3) reduce partials -> T1/T2 split halves
    reduceT<<<dim3(128, B_, 2), 256>>>(Pp, T1b, T1s, T2b, T2s);

    // 4) KE/VF split-K partials (256 CTAs, NK=8)
    kevf2p<<<256, 256, GEMM_SMEM>>>(T1b, T1s, T2b, T2s, Wkb, Wks, Wvb, Wvs, Pp);

    // 5) reduce + bias -> KE/VF split halves
    reduceKV<<<dim3(128, B_, 2), 256>>>(Pp, be, bf, KEbp, KEsp, VFbp, VFsp);

    // 6) fused attention -> O fp16
    attn_mma<<<dim3(N_ / 128, H_, B_), 256, ATT_SMEM>>>(Qb, KEbp, KEsp, VFbp, VFsp, Obp);

    // 7) out = Ob * Wob^T + bo (single-term)
    out_gemm<<<dim3(8, 64), 256, GEMM_SMEM>>>(Obp, Wob, bo, out);
}

// round 16
// speedup vs baseline: 1.7219x; 1.1589x over previous
#include <cuda_runtime.h>
#include <cuda_fp16.h>
#include <cstdint>

#define B_  2
#define N_  4096
#define C_  1024
#define H_  16
#define D_  64
#define K_  256
#define HD_ 1024
#define M_  8192

// ---------------- persistent split (big/small) fp16 buffers -------------
__device__ __half h_Xb [M_ * C_],    h_Xs [M_ * C_];
__device__ __half h_Xtb[B_ * C_ * N_], h_Xts[B_ * C_ * N_];   // X^T per batch
__device__ __half h_Wqb[HD_ * C_];
__device__ __half h_Wqs[HD_ * C_];     // still produced by split (unused)
__device__ __half h_Wkb[HD_ * C_],   h_Wks[HD_ * C_];
__device__ __half h_Wvb[HD_ * C_],   h_Wvs[HD_ * C_];
__device__ __half h_Web[K_ * N_],    h_Wes[K_ * N_];
__device__ __half h_Wfb[K_ * N_],    h_Wfs[K_ * N_];
__device__ __half h_Wob[C_ * HD_],   h_Wos[C_ * HD_];
__device__ __half h_Qb [M_ * HD_];
__device__ __half h_T1b[B_ * K_ * HD_], h_T1s[B_ * K_ * HD_];
__device__ __half h_T2b[B_ * K_ * HD_], h_T2s[B_ * K_ * HD_];
__device__ __half h_KEb[B_ * K_ * HD_];
__device__ __half h_VFb[B_ * HD_ * K_], h_VFs[B_ * HD_ * K_];
__device__ __half h_Ob [M_ * HD_];
__device__ float  g_part[16 * K_ * HD_];

#define DEV __device__ __forceinline__

DEV uint32_t su32(const void* p) {
    uint32_t a;
    asm("{ .reg .u64 t; cvta.to.shared.u64 t, %1; cvt.u32.u64 %0, t; }" : "=r"(a) : "l"(p));
    return a;
}
DEV void splitf(float x, float y, uint32_t& bo, uint32_t& so) {
    __half hx = __float2half_rn(x), hy = __float2half_rn(y);
    __half2 hb = __halves2half2(hx, hy);
    bo = *(uint32_t*)&hb;
    __half2 hs = __floats2half2_rn(x - __half2float(hx), y - __half2float(hy));
    so = *(uint32_t*)&hs;
}
DEV uint32_t packh2(float x, float y) {
    __half2 h = __floats2half2_rn(x, y);
    return *(uint32_t*)&h;
}

#define CP16(dst, src) asm volatile("cp.async.cg.shared.global [%0], [%1], 16;" :: "r"(dst), "l"(src) : "memory")
#define CPCOMMIT() asm volatile("cp.async.commit_group;" ::: "memory")
#define CPWAIT(n)  asm volatile("cp.async.wait_group %0;" :: "n"(n) : "memory")

#define LDM4(r, a) \
    asm volatile("ldmatrix.sync.aligned.m8n8.x4.shared.b16 {%0,%1,%2,%3}, [%4];" \
        : "=r"((r)[0]), "=r"((r)[1]), "=r"((r)[2]), "=r"((r)[3]) : "r"(a))

DEV void mma16816(float* d, const uint32_t* a, const uint32_t* b) {
    asm volatile("mma.sync.aligned.m16n8k16.row.col.f32.f16.f16.f32 "
        "{%0,%1,%2,%3}, {%4,%5,%6,%7}, {%8,%9}, {%0,%1,%2,%3};"
        : "+f"(d[0]), "+f"(d[1]), "+f"(d[2]), "+f"(d[3])
        : "r"(a[0]), "r"(a[1]), "r"(a[2]), "r"(a[3]), "r"(b[0]), "r"(b[1]));
}

DEV uint32_t tswz(int r, int ch) { return (r << 6) | (((ch ^ ((r >> 1) & 3)) & 3) << 4); }

// ==========================================================================
// split pass: X (with transpose, 64x64 tiles, 2048 blocks) + 6 weights
// ==========================================================================
__global__ void split_all(
    const float* X,  __half* Xb,  __half* Xs, __half* Xtb, __half* Xts,
    const float* W0, __half* W0b, __half* W0s,
    const float* W1, __half* W1b, __half* W1s,
    const float* W2, __half* W2b, __half* W2s,
    const float* W3, __half* W3b, __half* W3s,
    const float* W4, __half* W4b, __half* W4s,
    const float* W5, __half* W5b, __half* W5s)
{
    __shared__ float sm[64][68];
    const int bid = blockIdx.x, tid = threadIdx.x;
    if (bid < 2048) {
        const int b = bid >> 10, t = bid & 1023;
        const int n0 = (t >> 4) * 64, c0 = (t & 15) * 64;
        const int r = tid >> 2, q = tid & 3;
        const size_t gf4 = (((size_t)(b * 4096 + n0 + r)) * 1024 + c0) >> 2;
#pragma unroll
        for (int j = 0; j < 4; j++) {
            const int cf4 = q + j * 4;
            float4 v = ((const float4*)X)[gf4 + cf4];
            *(float4*)&sm[r][cf4 * 4] = v;
            uint32_t b0, s0, b1, s1;
            splitf(v.x, v.y, b0, s0);
            splitf(v.z, v.w, b1, s1);
            ((uint2*)Xb)[gf4 + cf4] = make_uint2(b0, b1);
            ((uint2*)Xs)[gf4 + cf4] = make_uint2(s0, s1);
        }
        __syncthreads();
        const size_t tf4 = (((size_t)(b * 1024 + c0 + r)) * 4096 + n0) >> 2;
#pragma unroll
        for (int j = 0; j < 4; j++) {
            const int nf4 = q + j * 4;
            const float f0 = sm[nf4 * 4 + 0][r];
            const float f1 = sm[nf4 * 4 + 1][r];
            const float f2 = sm[nf4 * 4 + 2][r];
            const float f3 = sm[nf4 * 4 + 3][r];
            uint32_t b0, s0, b1, s1;
            splitf(f0, f1, b0, s0);
            splitf(f2, f3, b1, s1);
            ((uint2*)Xtb)[tf4 + nf4] = make_uint2(b0, b1);
            ((uint2*)Xts)[tf4 + nf4] = make_uint2(s0, s1);
        }
    } else {
        const int t = bid - 2048, w = t >> 8, base = t & 255;
        const float* in = (w == 0) ? W0 : (w == 1) ? W1 : (w == 2) ? W2
                        : (w == 3) ? W3 : (w == 4) ? W4 : W5;
        __half* ob = (w == 0) ? W0b : (w == 1) ? W1b : (w == 2) ? W2b
                   : (w == 3) ? W3b : (w == 4) ? W4b : W5b;
        __half* os = (w == 0) ? W0s : (w == 1) ? W1s : (w == 2) ? W2s
                   : (w == 3) ? W3s : (w == 4) ? W4s : W5s;
        const int i0 = base * 1024 + tid;
        float4 v[4];
#pragma unroll
        for (int j = 0; j < 4; j++) v[j] = ((const float4*)in)[i0 + j * 256];
#pragma unroll
        for (int j = 0; j < 4; j++) {
            uint32_t b0, s0, b1, s1;
            splitf(v[j].x, v[j].y, b0, s0);
            splitf(v[j].z, v[j].w, b1, s1);
            ((uint2*)ob)[i0 + j * 256] = make_uint2(b0, b1);
            ((uint2*)os)[i0 + j * 256] = make_uint2(s0, s1);
        }
    }
}

// ==========================================================================
// GEMM body (runtime NK).
//   TERMS=1: C = Ab*Bb^T; TERMS=2: C = Ab*(Bb+Bs)^T;
//   TERMS=3: C = (Ab+As)*Bb^T + Ab*Bs^T
// EPI: 0=fp32, 1=split pair, 2=big only. BIAS: 0/1 col/2 row
// ==========================================================================
#define GEMM_SMEM 98304

template<int EPI, int BIAS, int TERMS>
DEV void gemm_body(const __half* __restrict__ Agb, const __half* __restrict__ Ags,
                   const __half* __restrict__ Bgb, const __half* __restrict__ Bgs,
                   const float* __restrict__ bias,
                   float* __restrict__ Cf,
                   __half* __restrict__ Cbh, __half* __restrict__ Csh,
                   int ldA, int ldB, int ldC,
                   int crow0, int ccol0, int NK, __half* sh)
{
    constexpr int SST  = (TERMS == 3) ? 32768 : (TERMS == 2) ? 24576 : 16384;
    constexpr int NS   = (TERMS == 3) ? 3 : 4;
    constexpr int OFFB = (TERMS == 3) ? 16384 : 8192;

    const int tid = threadIdx.x, wid = tid >> 5, lane = tid & 31;
    const uint32_t shb = su32(sh);
    const int wm = (wid >> 2) * 64, wn = (wid & 3) * 32;

    float acc[4][4][4];
#pragma unroll
    for (int m = 0; m < 4; m++)
#pragma unroll
        for (int n = 0; n < 4; n++)
#pragma unroll
            for (int j = 0; j < 4; j++) acc[m][n][j] = 0.f;

    auto PREFETCH = [&](int kt, int s) {
        const uint32_t st = shb + s * SST;
        const int kc = kt * 32;
#pragma unroll
        for (int p = 0; p < 2; p++) {
            const int id = p * 256 + tid;
            const int r = id >> 2, c = id & 3;
            const uint32_t d = st + tswz(r, c);
            const size_t ga = (size_t)r * ldA + kc + c * 8;
            const size_t gb = (size_t)r * ldB + kc + c * 8;
            CP16(d, Agb + ga);
            if constexpr (TERMS == 3) CP16(d + 8192, Ags + ga);
            CP16(d + OFFB, Bgb + gb);
            if constexpr (TERMS >= 2) CP16(d + OFFB + 8192, Bgs + gb);
        }
    };

    auto COMPUTE = [&](int s) {
        const uint32_t base = shb + s * SST;
#pragma unroll
        for (int ks2 = 0; ks2 < 2; ks2++) {
            uint32_t ab[4][4], as_[4][4];
#pragma unroll
            for (int m = 0; m < 4; m++) {
                const int r = wm + m * 16 + (lane & 15);
                const int ch = ks2 * 2 + (lane >> 4);
                LDM4(ab[m], base + tswz(r, ch));
                if constexpr (TERMS == 3) LDM4(as_[m], base + 8192 + tswz(r, ch));
            }
#pragma unroll
            for (int np = 0; np < 2; np++) {
                const int r = wn + np * 16 + (lane & 7) + 8 * (lane >> 4);
                const int ch = ks2 * 2 + ((lane >> 3) & 1);
                const uint32_t bd = base + OFFB + tswz(r, ch);
                uint32_t bb[4], bs[4];
                LDM4(bb, bd);
                if constexpr (TERMS >= 2) LDM4(bs, bd + 8192);
#pragma unroll
                for (int m = 0; m < 4; m++) mma16816(acc[m][2 * np],     ab[m], bb);
#pragma unroll
                for (int m = 0; m < 4; m++) mma16816(acc[m][2 * np + 1], ab[m], bb + 2);
                if constexpr (TERMS >= 2) {
#pragma unroll
                    for (int m = 0; m < 4; m++) mma16816(acc[m][2 * np],     ab[m], bs);
#pragma unroll
                    for (int m = 0; m < 4; m++) mma16816(acc[m][2 * np + 1], ab[m], bs + 2);
                }
                if constexpr (TERMS == 3) {
#pragma unroll
                    for (int m = 0; m < 4; m++) mma16816(acc[m][2 * np],     as_[m], bb);
#pragma unroll
                    for (int m = 0; m < 4; m++) mma16816(acc[m][2 * np + 1], as_[m], bb + 2);
                }
            }
        }
    };

#pragma unroll
    for (int s = 0; s < NS - 1; s++) { PREFETCH(s, s); CPCOMMIT(); }
    int sc = 0, sp = NS - 1;
    for (int kt = 0; kt < NK; kt++) {
        if (kt + NS - 1 < NK) CPWAIT(NS - 2); else CPWAIT(0);
        __syncthreads();
        if (kt + NS - 1 < NK) { PREFETCH(kt + NS - 1, sp); CPCOMMIT(); }
        COMPUTE(sc);
        sc = (sc + 1 == NS) ? 0 : sc + 1;
        sp = (sp + 1 == NS) ? 0 : sp + 1;
    }

    const int row0 = crow0 + wm + (lane >> 2);
    const int col0 = ccol0 + wn + 2 * (lane & 3);
#pragma unroll
    for (int m = 0; m < 4; m++) {
#pragma unroll
        for (int n = 0; n < 4; n++) {
            const int r = row0 + m * 16, c = col0 + n * 8;
            float v0 = acc[m][n][0], v1 = acc[m][n][1];
            float v2 = acc[m][n][2], v3 = acc[m][n][3];
            if (BIAS == 1) {
                const float bc0 = __ldg(&bias[c]), bc1 = __ldg(&bias[c + 1]);
                v0 += bc0; v1 += bc1; v2 += bc0; v3 += bc1;
            } else if (BIAS == 2) {
                const float br0 = __ldg(&bias[r]), br8 = __ldg(&bias[r + 8]);
                v0 += br0; v1 += br0; v2 += br8; v3 += br8;
            }
            if (EPI == 0) {
                *(float2*)&Cf[(size_t)r * ldC + c]       = make_float2(v0, v1);
                *(float2*)&Cf[(size_t)(r + 8) * ldC + c] = make_float2(v2, v3);
            } else if (EPI == 1) {
                uint32_t b0, s0, b1, s1;
                splitf(v0, v1, b0, s0);
                splitf(v2, v3, b1, s1);
                *(uint32_t*)&Cbh[(size_t)r * ldC + c]       = b0;
                *(uint32_t*)&Csh[(size_t)r * ldC + c]       = s0;
                *(uint32_t*)&Cbh[(size_t)(r + 8) * ldC + c] = b1;
                *(uint32_t*)&Csh[(size_t)(r + 8) * ldC + c] = s1;
            } else {
                *(uint32_t*)&Cbh[(size_t)r * ldC + c]       = packh2(v0, v1);
                *(uint32_t*)&Cbh[(size_t)(r + 8) * ldC + c] = packh2(v2, v3);
            }
        }
    }
}

// ==========================================================================
// merged Q + T1/T2: 768 CTAs
//   [0,512):   Q = Xb * Wqb^T (1-term, big-only out)
//   [512,768): T1/T2 split-K partials (3-term, fp32 out)
// ==========================================================================
__global__ void __launch_bounds__(256, 2)
qt12_gemm(const __half* __restrict__ Xb,
          const __half* __restrict__ Wqb,
          const __half* __restrict__ Web, const __half* __restrict__ Wes,
          const __half* __restrict__ Wfb, const __half* __restrict__ Wfs,
          const __half* __restrict__ Xtb, const __half* __restrict__ Xts,
          __half* Qb, float* part)
{
    extern __shared__ __half sh[];
    const int idx = blockIdx.x;
    if (idx < 512) {
        const int bx = idx & 7, by = idx >> 3;
        gemm_body<2, 0, 1>(Xb + (size_t)by * 128 * 1024, nullptr,
                           Wqb + (size_t)bx * 128 * 1024, nullptr,
                           nullptr, nullptr, Qb, nullptr,
                           1024, 1024, 1024, by * 128, bx * 128, 32, sh);
    } else {
        const int t = idx - 512;
        const int which = t >> 7, u = t & 127;
        const int z = u >> 4, r = u & 15;
        const int b = z >> 2, ks = z & 3;
        const int by = r >> 3, bx = r & 7;
        const __half* A  = (which ? Wfb : Web) + ks * 1024 + (size_t)by * 128 * 4096;
        const __half* As = (which ? Wfs : Wes) + ks * 1024 + (size_t)by * 128 * 4096;
        const __half* Bb = Xtb + (size_t)b * C_ * N_ + ks * 1024 + (size_t)bx * 128 * 4096;
        const __half* Bs = Xts + (size_t)b * C_ * N_ + ks * 1024 + (size_t)bx * 128 * 4096;
        gemm_body<0, 0, 3>(A, As, Bb, Bs, nullptr,
                           part + (size_t)(which * 8 + z) * K_ * HD_, nullptr, nullptr,
                           4096, 4096, 1024, by * 128, bx * 128, 32, sh);
    }
}

// ==========================================================================
// reduce T1/T2 partials -> split halves; 2 chunks/thread
// ==========================================================================
__global__ void reduceT(const float* __restrict__ part,
                        __half* T1b, __half* T1s, __half* T2b, __half* T2s)
{
    const int per = (K_ * HD_) / 4;
    const int b = blockIdx.y, which = blockIdx.z;
    __half* ob = which ? T2b : T1b;
    __half* os = which ? T2s : T1s;
    const float4* p = (const float4*)(part + (size_t)which * 8 * K_ * HD_)
                      + (size_t)b * 4 * per;
    const int i0 = blockIdx.x * 512 + threadIdx.x;
    float4 v[2][4];
#pragma unroll
    for (int u = 0; u < 2; u++) {
        const int i = i0 + u * 256;
        v[u][0] = p[i];
        v[u][1] = p[per + i];
        v[u][2] = p[2 * per + i];
        v[u][3] = p[3 * per + i];
    }
#pragma unroll
    for (int u = 0; u < 2; u++) {
        const int i = i0 + u * 256;
        float4 a = v[u][0];
        a.x += v[u][1].x + v[u][2].x + v[u][3].x;
        a.y += v[u][1].y + v[u][2].y + v[u][3].y;
        a.z += v[u][1].z + v[u][2].z + v[u][3].z;
        a.w += v[u][1].w + v[u][2].w + v[u][3].w;
        uint32_t b0, s0, b1, s1;
        splitf(a.x, a.y, b0, s0);
        splitf(a.z, a.w, b1, s1);
        ((uint2*)ob)[(size_t)b * per + i] = make_uint2(b0, b1);
        ((uint2*)os)[(size_t)b * per + i] = make_uint2(s0, s1);
    }
}

// ==========================================================================
// KE/VF split-K partials (3-term): 256 CTAs, K=1024 -> 4x256 (NK=8)
// ==========================================================================
__global__ void __launch_bounds__(256)
kevf2p(const __half* __restrict__ T1b, const __half* __restrict__ T1s,
       const __half* __restrict__ T2b, const __half* __restrict__ T2s,
       const __half* __restrict__ Wkb, const __half* __restrict__ Wks,
       const __half* __restrict__ Wvb, const __half* __restrict__ Wvs,
       float* part)
{
    extern __shared__ __half sh[];
    const int idx = blockIdx.x;
    if (idx < 128) {
        const int bx = idx & 7, by = (idx >> 3) & 1, z = idx >> 4;
        const int b = z >> 2, ks = z & 3;
        const __half* A  = T1b + (size_t)b * K_ * HD_ + (size_t)by * 128 * 1024 + ks * 256;
        const __half* As = T1s + (size_t)b * K_ * HD_ + (size_t)by * 128 * 1024 + ks * 256;
        const __half* Bb = Wkb + (size_t)bx * 128 * 1024 + ks * 256;
        const __half* Bs = Wks + (size_t)bx * 128 * 1024 + ks * 256;
        gemm_body<0, 0, 3>(A, As, Bb, Bs, nullptr,
                           part + (size_t)z * K_ * HD_, nullptr, nullptr,
                           1024, 1024, 1024, by * 128, bx * 128, 8, sh);
    } else {
        const int t = idx - 128;
        const int bx = t & 1, by = (t >> 1) & 7, z = t >> 4;
        const int b = z >> 2, ks = z & 3;
        const __half* A  = Wvb + (size_t)by * 128 * 1024 + ks * 256;
        const __half* As = Wvs + (size_t)by * 128 * 1024 + ks * 256;
        const __half* Bb = T2b + (size_t)b * K_ * HD_ + (size_t)bx * 128 * 1024 + ks * 256;
        const __half* Bs = T2s + (size_t)b * K_ * HD_ + (size_t)bx * 128 * 1024 + ks * 256;
        gemm_body<0, 0, 3>(A, As, Bb, Bs, nullptr,
                           part + (size_t)(8 + z) * K_ * HD_, nullptr, nullptr,
                           1024, 1024, 256, by * 128, bx * 128, 8, sh);
    }
}

// ==========================================================================
// reduce KE/VF partials + bias (z=0: KE rowbias, big only; z=1: VF colbias, pair)
// ==========================================================================
__global__ void reduceKV(const float* __restrict__ part,
                         const float* __restrict__ be, const float* __restrict__ bf,
                         __half* KEb, __half* VFb, __half* VFs)
{
    const int per = (K_ * HD_) / 4;
    const int b = blockIdx.y, which = blockIdx.z;
    const float* bias = which ? bf : be;
    const float4* p = (const float4*)(part + (size_t)which * 8 * K_ * HD_)
                      + (size_t)b * 4 * per;
    const int i0 = blockIdx.x * 512 + threadIdx.x;
    float4 v[2][4];
#pragma unroll
    for (int u = 0; u < 2; u++) {
        const int i = i0 + u * 256;
        v[u][0] = p[i];
        v[u][1] = p[per + i];
        v[u][2] = p[2 * per + i];
        v[u][3] = p[3 * per + i];
    }
#pragma unroll
    for (int u = 0; u < 2; u++) {
        const int i = i0 + u * 256;
        float4 a = v[u][0];
        a.x += v[u][1].x + v[u][2].x + v[u][3].x;
        a.y += v[u][1].y + v[u][2].y + v[u][3].y;
        a.z += v[u][1].z + v[u][2].z + v[u][3].z;
        a.w += v[u][1].w + v[u][2].w + v[u][3].w;
        const int e = i * 4;
        if (which) {           // VF: [1024,256], per-column bias bf, split pair
            const int c = e & (K_ - 1);
            a.x += bias[c]; a.y += bias[c + 1]; a.z += bias[c + 2]; a.w += bias[c + 3];
            uint32_t b0, s0, b1, s1;
            splitf(a.x, a.y, b0, s0);
            splitf(a.z, a.w, b1, s1);
            ((uint2*)VFb)[(size_t)b * per + i] = make_uint2(b0, b1);
            ((uint2*)VFs)[(size_t)b * per + i] = make_uint2(s0, s1);
        } else {               // KE: [256,1024], per-row bias be, big only
            const float bb = bias[e >> 10];
            a.x += bb; a.y += bb; a.z += bb; a.w += bb;
            ((uint2*)KEb)[(size_t)b * per + i] =
                make_uint2(packh2(a.x, a.y), packh2(a.z, a.w));
        }
    }
}

// ==========================================================================
// out projection: single-term, 512 CTAs
// ==========================================================================
__global__ void __launch_bounds__(256, 2)
out_gemm(const __half* __restrict__ Ob_,
         const __half* __restrict__ Wob,
         const float* __restrict__ bo, float* __restrict__ out)
{
    extern __shared__ __half sh[];
    const int bx = blockIdx.x, by = blockIdx.y;
    gemm_body<0, 1, 1>(Ob_ + (size_t)by * 128 * 1024, nullptr,
                       Wob + (size_t)bx * 128 * 1024, nullptr,
                       bo, out, nullptr, nullptr,
                       1024, 1024, 1024, by * 128, bx * 128, 32, sh);
}

// ==========================================================================
// Fused attention: CTA = (128 rows, head h, batch b), 8 warps
// scores = Qb * KEb^T (1-term); softmax; O = P16 * (VFb+VFs)^T; O fp16
// ==========================================================================
#define QSTR 72
#define VSTR 264
#define OQB 0
#define OKB (128 * QSTR)
#define OVB (OKB + 256 * QSTR)
#define OVS (OVB + 64 * VSTR)
#define ATT_SMEM ((OVS + 64 * VSTR) * 2)   // 122880 bytes

__global__ void __launch_bounds__(256, 1)
attn_mma(const __half* __restrict__ Qb, const __half* __restrict__ KEb,
         const __half* __restrict__ VFb, const __half* __restrict__ VFs,
         __half* __restrict__ Ob)
{
    extern __shared__ __half sh[];
    const int tid = threadIdx.x, wid = tid >> 5, lane = tid & 31;
    const int b = blockIdx.z, h = blockIdx.y, n0 = blockIdx.x * 128;
    const uint32_t shb = su32(sh);

    const __half* Qgb = Qb  + ((size_t)(b * N_ + n0)) * HD_ + h * D_;
    const __half* Kgb = KEb + ((size_t)b * K_) * HD_ + h * D_;
    const __half* Vgb = VFb + ((size_t)(b * HD_ + h * D_)) * K_;
    const __half* Vgs = VFs + ((size_t)(b * HD_ + h * D_)) * K_;

#pragma unroll
    for (int p = 0; p < 4; p++) {
        const int id = p * 256 + tid;
        const int r = id >> 3, c = id & 7;
        CP16(shb + OQB * 2 + (r * QSTR + c * 8) * 2, Qgb + (size_t)r * HD_ + c * 8);
    }
#pragma unroll
    for (int p = 0; p < 8; p++) {
        const int id = p * 256 + tid;
        const int r = id >> 3, c = id & 7;
        CP16(shb + OKB * 2 + (r * QSTR + c * 8) * 2, Kgb + (size_t)r * HD_ + c * 8);
    }
#pragma unroll
    for (int p = 0; p < 8; p++) {
        const int id = p * 256 + tid;
        const int r = id >> 5, c = id & 31;
        const size_t g = (size_t)r * K_ + c * 8;
        const uint32_t d = (r * VSTR + c * 8) * 2;
        CP16(shb + OVB * 2 + d, Vgb + g);
        CP16(shb + OVS * 2 + d, Vgs + g);
    }
    CPCOMMIT();
    CPWAIT(0);
    __syncthreads();

    float sacc[32][4];
#pragma unroll
    for (int j = 0; j < 32; j++)
#pragma unroll
        for (int q = 0; q < 4; q++) sacc[j][q] = 0.f;

    const int r0 = wid * 16;
    const uint32_t aoff = ((r0 + (lane & 15)) * QSTR + 8 * (lane >> 4)) * 2;
    const uint32_t boff = (((lane & 7) + 8 * (lane >> 4)) * QSTR + 8 * ((lane >> 3) & 1)) * 2;

#pragma unroll
    for (int ks = 0; ks < 64; ks += 16) {
        uint32_t ab[4];
        LDM4(ab, shb + OQB * 2 + aoff + ks * 2);
#pragma unroll
        for (int np = 0; np < 16; np++) {
            uint32_t kb[4];
            LDM4(kb, shb + OKB * 2 + boff + (np * 16 * QSTR + ks) * 2);
            mma16816(sacc[2 * np],     ab, kb);
            mma16816(sacc[2 * np + 1], ab, kb + 2);
        }
    }

    float mx0 = -1e30f, mx1 = -1e30f;
#pragma unroll
    for (int j = 0; j < 32; j++) {
        mx0 = fmaxf(mx0, fmaxf(sacc[j][0], sacc[j][1]));
        mx1 = fmaxf(mx1, fmaxf(sacc[j][2], sacc[j][3]));
    }
    mx0 = fmaxf(mx0, __shfl_xor_sync(0xffffffffu, mx0, 1));
    mx0 = fmaxf(mx0, __shfl_xor_sync(0xffffffffu, mx0, 2));
    mx1 = fmaxf(mx1, __shfl_xor_sync(0xffffffffu, mx1, 1));
    mx1 = fmaxf(mx1, __shfl_xor_sync(0xffffffffu, mx1, 2));
    float sum0 = 0.f, sum1 = 0.f;
#pragma unroll
    for (int j = 0; j < 32; j++) {
        float e0 = __expf((sacc[j][0] - mx0) * 0.125f);
        float e1 = __expf((sacc[j][1] - mx0) * 0.125f);
        float e2 = __expf((sacc[j][2] - mx1) * 0.125f);
        float e3 = __expf((sacc[j][3] - mx1) * 0.125f);
        sacc[j][0] = e0; sacc[j][1] = e1; sacc[j][2] = e2; sacc[j][3] = e3;
        sum0 += e0 + e1; sum1 += e2 + e3;
    }
    sum0 += __shfl_xor_sync(0xffffffffu, sum0, 1);
    sum0 += __shfl_xor_sync(0xffffffffu, sum0, 2);
    sum1 += __shfl_xor_sync(0xffffffffu, sum1, 1);
    sum1 += __shfl_xor_sync(0xffffffffu, sum1, 2);
    const float inv0 = 1.0f / sum0, inv1 = 1.0f / sum1;
#pragma unroll
    for (int j = 0; j < 32; j++) {
        sacc[j][0] *= inv0; sacc[j][1] *= inv0;
        sacc[j][2] *= inv1; sacc[j][3] *= inv1;
    }

    float oacc[8][4];
#pragma unroll
    for (int n = 0; n < 8; n++)
#pragma unroll
        for (int q = 0; q < 4; q++) oacc[n][q] = 0.f;

#pragma unroll
    for (int kt = 0; kt < 16; kt++) {
        uint32_t pa[4];
        pa[0] = packh2(sacc[2 * kt][0],     sacc[2 * kt][1]);
        pa[1] = packh2(sacc[2 * kt][2],     sacc[2 * kt][3]);
        pa[2] = packh2(sacc[2 * kt + 1][0], sacc[2 * kt + 1][1]);
        pa[3] = packh2(sacc[2 * kt + 1][2], sacc[2 * kt + 1][3]);
#pragma unroll
        for (int np = 0; np < 4; np++) {
            const uint32_t bd = (((lane & 7) + 8 * (lane >> 4) + np * 16) * VSTR
                                 + kt * 16 + 8 * ((lane >> 3) & 1)) * 2;
            uint32_t vb[4], vs[4];
            LDM4(vb, shb + OVB * 2 + bd);
            LDM4(vs, shb + OVS * 2 + bd);
            mma16816(oacc[2 * np],     pa, vb);
            mma16816(oacc[2 * np + 1], pa, vb + 2);
            mma16816(oacc[2 * np],     pa, vs);
            mma16816(oacc[2 * np + 1], pa, vs + 2);
        }
    }

    const int orow = n0 + r0 + (lane >> 2);
    const int ocol = h * D_ + 2 * (lane & 3);
    __half* Obp = Ob + ((size_t)b * N_) * HD_;
#pragma unroll
    for (int n = 0; n < 8; n++) {
        *(uint32_t*)&Obp[(size_t)orow * HD_ + ocol + n * 8]       = packh2(oacc[n][0], oacc[n][1]);
        *(uint32_t*)&Obp[(size_t)(orow + 8) * HD_ + ocol + n * 8] = packh2(oacc[n][2], oacc[n][3]);
    }
}

// ==========================================================================
extern "C" void kernel_launch(void* const* d_in, const int* in_sizes, int n_in,
                              void* d_out, int out_size)
{
    const float* X  = (const float*)d_in[0];
    const float* Wq = (const float*)d_in[1];
    const float* Wk = (const float*)d_in[2];
    const float* Wv = (const float*)d_in[3];
    const float* We = (const float*)d_in[4];
    const float* be = (const float*)d_in[5];
    const float* Wf = (const float*)d_in[6];
    const float* bf = (const float*)d_in[7];
    const float* Wo = (const float*)d_in[8];
    const float* bo = (const float*)d_in[9];
    float* out = (float*)d_out;

    __half *Xb, *Xs, *Xtb, *Xts, *Wqb, *Wqs, *Wkb, *Wks, *Wvb, *Wvs;
    __half *Web, *Wes, *Wfb, *Wfs, *Wob, *Wos, *Qb;
    __half *T1b, *T1s, *T2b, *T2s, *KEbp, *VFbp, *VFsp, *Obp;
    float* Pp;
    cudaGetSymbolAddress((void**)&Xb,  h_Xb);   cudaGetSymbolAddress((void**)&Xs,  h_Xs);
    cudaGetSymbolAddress((void**)&Xtb, h_Xtb);  cudaGetSymbolAddress((void**)&Xts, h_Xts);
    cudaGetSymbolAddress((void**)&Wqb, h_Wqb);  cudaGetSymbolAddress((void**)&Wqs, h_Wqs);
    cudaGetSymbolAddress((void**)&Wkb, h_Wkb);  cudaGetSymbolAddress((void**)&Wks, h_Wks);
    cudaGetSymbolAddress((void**)&Wvb, h_Wvb);  cudaGetSymbolAddress((void**)&Wvs, h_Wvs);
    cudaGetSymbolAddress((void**)&Web, h_Web);  cudaGetSymbolAddress((void**)&Wes, h_Wes);
    cudaGetSymbolAddress((void**)&Wfb, h_Wfb);  cudaGetSymbolAddress((void**)&Wfs, h_Wfs);
    cudaGetSymbolAddress((void**)&Wob, h_Wob);  cudaGetSymbolAddress((void**)&Wos, h_Wos);
    cudaGetSymbolAddress((void**)&Qb,  h_Qb);
    cudaGetSymbolAddress((void**)&T1b, h_T1b);  cudaGetSymbolAddress((void**)&T1s, h_T1s);
    cudaGetSymbolAddress((void**)&T2b, h_T2b);  cudaGetSymbolAddress((void**)&T2s, h_T2s);
    cudaGetSymbolAddress((void**)&KEbp, h_KEb);
    cudaGetSymbolAddress((void**)&VFbp, h_VFb); cudaGetSymbolAddress((void**)&VFsp, h_VFs);
    cudaGetSymbolAddress((void**)&Obp, h_Ob);
    cudaGetSymbolAddress((void**)&Pp,  g_part);

    cudaFuncSetAttribute(qt12_gemm, cudaFuncAttributeMaxDynamicSharedMemorySize, GEMM_SMEM);
    cudaFuncSetAttribute(kevf2p,    cudaFuncAttributeMaxDynamicSharedMemorySize, GEMM_SMEM);
    cudaFuncSetAttribute(out_gemm,  cudaFuncAttributeMaxDynamicSharedMemorySize, GEMM_SMEM);
    cudaFuncSetAttribute(attn_mma,  cudaFuncAttributeMaxDynamicSharedMemorySize, ATT_SMEM);

    // 1) split X (+transpose) and all weights
    split_all<<<2048 + 6 * 256, 256>>>(
        X, Xb, Xs, Xtb, Xts,
        Wq, Wqb, Wqs, Wk, Wkb, Wks, Wv, Wvb, Wvs,
        We, Web, Wes, Wf, Wfb, Wfs, Wo, Wob, Wos);

    // 2) merged Q (1-term) + T1/T2 (768 CTAs)
    qt12_gemm<<<768, 256, GEMM_SMEM>>>(Xb, Wqb, Web, Wes, Wfb, Wfs,
                                       Xtb, Xts, Qb, Pp);

    // 3) reduce partials -> T1/T2 split halves
    reduceT<<<dim3(128, B_, 2), 256>>>(Pp, T1b, T1s, T2b, T2s);

    // 4) KE/VF split-K partials (256 CTAs, NK=8)
    kevf2p<<<256, 256, GEMM_SMEM>>>(T1b, T1s, T2b, T2s, Wkb, Wks, Wvb, Wvs, Pp);

    // 5) reduce + bias -> KE big, VF split pair
    reduceKV<<<dim3(128, B_, 2), 256>>>(Pp, be, bf, KEbp, VFbp, VFsp);

    // 6) fused attention -> O fp16
    attn_mma<<<dim3(N_ / 128, H_, B_), 256, ATT_SMEM>>>(Qb, KEbp, VFbp, VFsp, Obp);

    // 7) out = Ob * Wob^T + bo (single-term)
    out_gemm<<<dim3(8, 64), 256, GEMM_SMEM>>>(Obp, Wob, bo, out);
}